// round 6
// baseline (speedup 1.0000x reference)
#include <cuda_runtime.h>
#include <math.h>
#include <stdint.h>

typedef unsigned long long ull;

// Problem constants
#define BB    32
#define TT    8192
#define NTOK  (BB * TT)      // 262144
#define NGRP  (NTOK / 4)     // 65536 groups of 4 tokens (one warp-pair each)

// ---------------------------------------------------------------------------
// Device-global scratch
// ---------------------------------------------------------------------------
__device__ float g_T2a[500 * 256];
__device__ float g_T2b[500 * 256];
__device__ float g_T3a[500 * 256];
__device__ float g_T3b[500 * 256];
__device__ float g_T3c[500 * 256];
__device__ float g_Val [(size_t)NTOK * 64];   // gated value (residual input)
__device__ float g_ValN[(size_t)NTOK * 64];   // conv-LN(gated value)*g+b

__device__ __forceinline__ float silu_f(float x) {
    return __fdividef(x, 1.0f + __expf(-x));
}
__device__ __forceinline__ float wsum(float v) {
#pragma unroll
    for (int m = 16; m > 0; m >>= 1) v += __shfl_xor_sync(0xffffffffu, v, m);
    return v;
}
__device__ __forceinline__ ull pack2(float lo, float hi) {
    return (ull)__float_as_uint(lo) | ((ull)__float_as_uint(hi) << 32);
}
__device__ __forceinline__ float f2sum(ull v) {
    return __uint_as_float((unsigned)v) + __uint_as_float((unsigned)(v >> 32));
}
// Packed fp32x2 FMA (Blackwell FFMA2; only reachable via PTX)
#define FMA2(acc, a, b) \
    asm("fma.rn.f32x2 %0, %1, %2, %0;" : "+l"(acc) : "l"(a), "l"(b))

#define PBAR() asm volatile("bar.sync %0, 64;" :: "r"(pairid + 1) : "memory")

// ---------------------------------------------------------------------------
// Kernel 1: per-vocab table precompute (unchanged, 20us)
// ---------------------------------------------------------------------------
__global__ void precompute_tables(const float* __restrict__ emb,
                                  const float* __restrict__ W1_2,
                                  const float* __restrict__ b1_2,
                                  const float* __restrict__ W1_3,
                                  const float* __restrict__ b1_3) {
    __shared__ float e[64];
    const int id = blockIdx.x;
    const int o  = threadIdx.x;
    if (o < 64) e[o] = emb[id * 64 + o];
    __syncthreads();

    float a2 = 0.f, b2 = 0.f, a3 = 0.f, b3 = 0.f, c3 = 0.f;
#pragma unroll 8
    for (int d = 0; d < 64; d++) {
        const float ev = e[d];
        a2 += ev * W1_2[d * 256 + o];
        b2 += ev * W1_2[(64 + d) * 256 + o];
        a3 += ev * W1_3[d * 256 + o];
        b3 += ev * W1_3[(64 + d) * 256 + o];
        c3 += ev * W1_3[(128 + d) * 256 + o];
    }
    g_T2a[id * 256 + o] = a2;
    g_T2b[id * 256 + o] = b2 + b1_2[o];
    g_T3a[id * 256 + o] = a3;
    g_T3b[id * 256 + o] = b3;
    g_T3c[id * 256 + o] = c3 + b1_3[o];
}

// ---------------------------------------------------------------------------
// Kernel 2: main fused kernel. 256 threads = 8 warps = 4 warp-pairs.
// A pair processes 4 tokens per iteration; the two warps col-split the GEMMs.
// Dynamic smem (floats):
//   [    0 : 16384)  W2_2 pair-packed  (ull idx: kp*64 + c, kp<128, c<64)
//   [16384 : 32768)  W2_3 pair-packed
//   [32768 : 49152)  key|val pair-packed (ull idx: kp*128 + c, kp<64, c<128)
//   [49152 : 53248)  hb: pair p at +p*1024  (4 tok x 256)   [also kv output]
//   [53248 : 55296)  eb: pair p at +p*512   (4 tok x 128)
// Total 55296 floats = 221184 B.
// ---------------------------------------------------------------------------
__global__ void __launch_bounds__(256, 1)
main_kernel(const int*   __restrict__ ids_g,
            const float* __restrict__ hidden,
            const float* __restrict__ W2_2g, const float* __restrict__ b2_2,
            const float* __restrict__ W2_3g, const float* __restrict__ b2_3,
            const float* __restrict__ keyW,  const float* __restrict__ keyb,
            const float* __restrict__ valW,  const float* __restrict__ valb,
            const float* __restrict__ n1g,   const float* __restrict__ n1b,
            const float* __restrict__ n2g,   const float* __restrict__ n2b,
            const float* __restrict__ cg,    const float* __restrict__ cb) {
    extern __shared__ float sm[];
    ull* W2au = (ull*)sm;
    ull* W2bu = (ull*)(sm + 16384);
    ull* KVu  = (ull*)(sm + 32768);

    const int tid    = threadIdx.x;
    const int wid    = tid >> 5;
    const int lane   = tid & 31;
    const int pairid = wid >> 1;
    const int sub    = wid & 1;

    float* hb  = sm + 49152 + pairid * 1024;
    float* eb  = sm + 53248 + pairid * 512;
    ull*   hbu = (ull*)hb;   // [tok*128 + kp]
    ull*   ebu = (ull*)eb;   // [tok*64  + kp]
    float* kvo = hb;         // kv output reuses hb

    // Stage pair-packed weights: pair (2kp, 2kp+1) of column c -> one u64.
    for (int i = tid; i < 8192; i += 256) {
        const int kp = i >> 6, c = i & 63;
        W2au[i] = pack2(W2_2g[kp * 128 + c], W2_2g[kp * 128 + 64 + c]);
        W2bu[i] = pack2(W2_3g[kp * 128 + c], W2_3g[kp * 128 + 64 + c]);
        const int kp2 = i >> 7, c2 = i & 127;
        float lo, hi;
        if (c2 < 64) { lo = keyW[kp2 * 128 + c2];      hi = keyW[kp2 * 128 + 64 + c2]; }
        else         { lo = valW[kp2 * 128 + c2 - 64]; hi = valW[kp2 * 128 + c2]; }
        KVu[i] = pack2(lo, hi);
    }
    __syncthreads();

    // Per-lane hoisted constants
    const int   c     = sub * 32 + lane;       // GEMM output column
    const float bias2 = b2_2[c];
    const float bias3 = b2_3[c];
    const float* kvbp = sub ? valb : keyb;
    const float kvb0  = kvbp[lane], kvb1 = kvbp[lane + 32];
    const float g1x = n1g[lane], g1y = n1g[lane + 32];
    const float o1x = n1b[lane], o1y = n1b[lane + 32];
    const float g2x = n2g[lane], g2y = n2g[lane + 32];
    const float o2x = n2b[lane], o2y = n2b[lane + 32];
    const float cgx = cg[lane],  cgy = cg[lane + 32];
    const float cbx = cb[lane],  cby = cb[lane + 32];
    const int   o0  = lane * 8;

    for (int grp = blockIdx.x * 4 + pairid; grp < NGRP; grp += gridDim.x * 4) {
        const int t0 = grp * 4;
        const int b  = t0 >> 13;
        const int p0 = t0 & 8191;

        PBAR();  // previous iteration's kvo reads complete

        int idx[6];
#pragma unroll
        for (int j = 0; j < 6; j++) {
            const int pp = p0 + j - 2;
            idx[j] = (pp >= 0) ? ids_g[b * TT + pp] : -1;
        }

        // -------- h2 build: this warp's 2 tokens --------
#pragma unroll
        for (int i = 0; i < 2; i++) {
            const int tok = sub * 2 + i;
            const float* rc = g_T2b + idx[tok + 2] * 256 + o0;
            float4 x0 = *(const float4*)rc;
            float4 x1 = *(const float4*)(rc + 4);
            const int ip = idx[tok + 1];
            if (ip >= 0) {
                const float* rp = g_T2a + ip * 256 + o0;
                const float4 y0 = *(const float4*)rp;
                const float4 y1 = *(const float4*)(rp + 4);
                x0.x += y0.x; x0.y += y0.y; x0.z += y0.z; x0.w += y0.w;
                x1.x += y1.x; x1.y += y1.y; x1.z += y1.z; x1.w += y1.w;
            }
            x0.x = silu_f(x0.x); x0.y = silu_f(x0.y); x0.z = silu_f(x0.z); x0.w = silu_f(x0.w);
            x1.x = silu_f(x1.x); x1.y = silu_f(x1.y); x1.z = silu_f(x1.z); x1.w = silu_f(x1.w);
            *(float4*)(hb + tok * 256 + o0)     = x0;
            *(float4*)(hb + tok * 256 + o0 + 4) = x1;
        }
        PBAR();

        // -------- out2 = silu(h2) @ W2_2 (col-split, all 4 tokens) --------
        {
            ull a0 = 0, a1 = 0, a2 = 0, a3 = 0;
#pragma unroll 8
            for (int kp = 0; kp < 128; kp += 2) {
                const ull wA = W2au[kp * 64 + c];
                const ull wB = W2au[kp * 64 + 64 + c];
                const ulonglong2 h0 = *(const ulonglong2*)(hbu + 0 * 128 + kp);
                const ulonglong2 h1 = *(const ulonglong2*)(hbu + 1 * 128 + kp);
                const ulonglong2 h2 = *(const ulonglong2*)(hbu + 2 * 128 + kp);
                const ulonglong2 h3 = *(const ulonglong2*)(hbu + 3 * 128 + kp);
                FMA2(a0, h0.x, wA); FMA2(a0, h0.y, wB);
                FMA2(a1, h1.x, wA); FMA2(a1, h1.y, wB);
                FMA2(a2, h2.x, wA); FMA2(a2, h2.y, wB);
                FMA2(a3, h3.x, wA); FMA2(a3, h3.y, wB);
            }
            eb[0 * 128 + c] = f2sum(a0) + bias2;
            eb[1 * 128 + c] = f2sum(a1) + bias2;
            eb[2 * 128 + c] = f2sum(a2) + bias2;
            eb[3 * 128 + c] = f2sum(a3) + bias2;
        }
        PBAR();  // hb reads done -> safe to rebuild

        // -------- h3 build --------
#pragma unroll
        for (int i = 0; i < 2; i++) {
            const int tok = sub * 2 + i;
            const float* rc = g_T3c + idx[tok + 2] * 256 + o0;
            float4 x0 = *(const float4*)rc;
            float4 x1 = *(const float4*)(rc + 4);
            const int i1 = idx[tok + 1];
            if (i1 >= 0) {
                const float* rp = g_T3b + i1 * 256 + o0;
                const float4 y0 = *(const float4*)rp;
                const float4 y1 = *(const float4*)(rp + 4);
                x0.x += y0.x; x0.y += y0.y; x0.z += y0.z; x0.w += y0.w;
                x1.x += y1.x; x1.y += y1.y; x1.z += y1.z; x1.w += y1.w;
            }
            const int i2 = idx[tok];
            if (i2 >= 0) {
                const float* rp = g_T3a + i2 * 256 + o0;
                const float4 y0 = *(const float4*)rp;
                const float4 y1 = *(const float4*)(rp + 4);
                x0.x += y0.x; x0.y += y0.y; x0.z += y0.z; x0.w += y0.w;
                x1.x += y1.x; x1.y += y1.y; x1.z += y1.z; x1.w += y1.w;
            }
            x0.x = silu_f(x0.x); x0.y = silu_f(x0.y); x0.z = silu_f(x0.z); x0.w = silu_f(x0.w);
            x1.x = silu_f(x1.x); x1.y = silu_f(x1.y); x1.z = silu_f(x1.z); x1.w = silu_f(x1.w);
            *(float4*)(hb + tok * 256 + o0)     = x0;
            *(float4*)(hb + tok * 256 + o0 + 4) = x1;
        }
        PBAR();

        // -------- out3 = silu(h3) @ W2_3 --------
        {
            ull a0 = 0, a1 = 0, a2 = 0, a3 = 0;
#pragma unroll 8
            for (int kp = 0; kp < 128; kp += 2) {
                const ull wA = W2bu[kp * 64 + c];
                const ull wB = W2bu[kp * 64 + 64 + c];
                const ulonglong2 h0 = *(const ulonglong2*)(hbu + 0 * 128 + kp);
                const ulonglong2 h1 = *(const ulonglong2*)(hbu + 1 * 128 + kp);
                const ulonglong2 h2 = *(const ulonglong2*)(hbu + 2 * 128 + kp);
                const ulonglong2 h3 = *(const ulonglong2*)(hbu + 3 * 128 + kp);
                FMA2(a0, h0.x, wA); FMA2(a0, h0.y, wB);
                FMA2(a1, h1.x, wA); FMA2(a1, h1.y, wB);
                FMA2(a2, h2.x, wA); FMA2(a2, h2.y, wB);
                FMA2(a3, h3.x, wA); FMA2(a3, h3.y, wB);
            }
            eb[0 * 128 + 64 + c] = f2sum(a0) + bias3;
            eb[1 * 128 + 64 + c] = f2sum(a1) + bias3;
            eb[2 * 128 + 64 + c] = f2sum(a2) + bias3;
            eb[3 * 128 + 64 + c] = f2sum(a3) + bias3;
        }
        PBAR();  // eb fully written by both warps; hb reads done

        // -------- k/v = emb @ [keyW|valW]; warp covers 64 of 128 out cols ---
        {
            const int ck = sub * 64 + lane;   // cols ck, ck+32
            ull a0 = 0, a1 = 0, a2 = 0, a3 = 0;   // col ck,   tok 0..3
            ull b0 = 0, b1 = 0, b2 = 0, b3 = 0;   // col ck+32
#pragma unroll 4
            for (int kp = 0; kp < 64; kp += 2) {
                const ull w0A = KVu[kp * 128 + ck];
                const ull w0B = KVu[kp * 128 + 128 + ck];
                const ull w1A = KVu[kp * 128 + 32 + ck];
                const ull w1B = KVu[kp * 128 + 160 + ck];
                const ulonglong2 e0 = *(const ulonglong2*)(ebu + 0 * 64 + kp);
                const ulonglong2 e1 = *(const ulonglong2*)(ebu + 1 * 64 + kp);
                const ulonglong2 e2 = *(const ulonglong2*)(ebu + 2 * 64 + kp);
                const ulonglong2 e3 = *(const ulonglong2*)(ebu + 3 * 64 + kp);
                FMA2(a0, e0.x, w0A); FMA2(a0, e0.y, w0B);
                FMA2(b0, e0.x, w1A); FMA2(b0, e0.y, w1B);
                FMA2(a1, e1.x, w0A); FMA2(a1, e1.y, w0B);
                FMA2(b1, e1.x, w1A); FMA2(b1, e1.y, w1B);
                FMA2(a2, e2.x, w0A); FMA2(a2, e2.y, w0B);
                FMA2(b2, e2.x, w1A); FMA2(b2, e2.y, w1B);
                FMA2(a3, e3.x, w0A); FMA2(a3, e3.y, w0B);
                FMA2(b3, e3.x, w1A); FMA2(b3, e3.y, w1B);
            }
            kvo[0 * 128 + ck]      = f2sum(a0) + kvb0;
            kvo[1 * 128 + ck]      = f2sum(a1) + kvb0;
            kvo[2 * 128 + ck]      = f2sum(a2) + kvb0;
            kvo[3 * 128 + ck]      = f2sum(a3) + kvb0;
            kvo[0 * 128 + ck + 32] = f2sum(b0) + kvb1;
            kvo[1 * 128 + ck + 32] = f2sum(b1) + kvb1;
            kvo[2 * 128 + ck + 32] = f2sum(b2) + kvb1;
            kvo[3 * 128 + ck + 32] = f2sum(b3) + kvb1;
        }
        PBAR();

        // -------- epilogue: LN(k), LN(hidden), gate, value, conv-LN --------
#pragma unroll
        for (int i = 0; i < 2; i++) {
            const int tok = sub * 2 + i;
            const float kd0 = kvo[tok * 128 + lane];
            const float kd1 = kvo[tok * 128 + 32 + lane];
            const float vd0 = kvo[tok * 128 + 64 + lane];
            const float vd1 = kvo[tok * 128 + 96 + lane];

            const float mk = wsum(kd0 + kd1) * (1.0f / 64.0f);
            const float qk = wsum(kd0 * kd0 + kd1 * kd1) * (1.0f / 64.0f);
            const float ik = rsqrtf(qk - mk * mk + 1e-5f);
            const float nk0 = (kd0 - mk) * ik * g1x + o1x;
            const float nk1 = (kd1 - mk) * ik * g1y + o1y;

            const float* hr = hidden + ((size_t)(t0 + tok)) * 64;
            const float hq0 = hr[lane];
            const float hq1 = hr[lane + 32];
            const float mh = wsum(hq0 + hq1) * (1.0f / 64.0f);
            const float qh = wsum(hq0 * hq0 + hq1 * hq1) * (1.0f / 64.0f);
            const float ih = rsqrtf(qh - mh * mh + 1e-5f);
            const float nq0 = (hq0 - mh) * ih * g2x + o2x;
            const float nq1 = (hq1 - mh) * ih * g2y + o2y;

            const float dp = wsum(nk0 * nq0 + nk1 * nq1) * 0.125f;
            const float sq = sqrtf(fmaxf(fabsf(dp), 1e-6f));
            const float gs = (dp > 0.f) ? sq : ((dp < 0.f) ? -sq : 0.f);
            const float gate = __fdividef(1.0f, 1.0f + __expf(-gs));

            const float gv0 = gate * vd0;
            const float gv1 = gate * vd1;
            float* vo = g_Val + ((size_t)(t0 + tok)) * 64;
            vo[lane]      = gv0;
            vo[lane + 32] = gv1;

            const float mv = wsum(gv0 + gv1) * (1.0f / 64.0f);
            const float qv = wsum(gv0 * gv0 + gv1 * gv1) * (1.0f / 64.0f);
            const float iv = rsqrtf(qv - mv * mv + 1e-5f);
            float* vn = g_ValN + ((size_t)(t0 + tok)) * 64;
            vn[lane]      = (gv0 - mv) * iv * cgx + cbx;
            vn[lane + 32] = (gv1 - mv) * iv * cgy + cby;
        }
    }
}

// ---------------------------------------------------------------------------
// Kernel 3: streaming causal dilated depthwise conv (LN precomputed).
// Thread = (token, dim-pair). out = Val[t] + silu(sum_j w[d,j]*ValN[t-9+3j,d])
// ---------------------------------------------------------------------------
__global__ void conv_kernel(const float* __restrict__ cw,
                            float* __restrict__ out) {
    const int g     = blockIdx.x * blockDim.x + threadIdx.x;
    const int token = g >> 5;
    const int d0    = (g & 31) * 2;
    const int p     = token & 8191;

    const float4 w0 = *(const float4*)(cw + d0 * 4);
    const float4 w1 = *(const float4*)(cw + d0 * 4 + 4);

    float y0 = 0.f, y1 = 0.f;
    const float* basen = g_ValN + (size_t)token * 64 + d0;
#pragma unroll
    for (int j = 0; j < 4; j++) {
        const int tp = p - 9 + 3 * j;
        if (tp >= 0) {
            const float2 v = *(const float2*)(basen + (long)(3 * j - 9) * 64);
            y0 += ((const float*)&w0)[j] * v.x;
            y1 += ((const float*)&w1)[j] * v.y;
        }
    }
    const float2 r = *(const float2*)(g_Val + (size_t)token * 64 + d0);
    const float2 res = make_float2(r.x + silu_f(y0), r.y + silu_f(y1));
    *(float2*)(out + (size_t)token * 64 + d0) = res;
}

// ---------------------------------------------------------------------------
// Host launcher
// ---------------------------------------------------------------------------
extern "C" void kernel_launch(void* const* d_in, const int* in_sizes, int n_in,
                              void* d_out, int out_size) {
    const float* hidden = (const float*)d_in[0];
    const int*   ids    = (const int*)d_in[1];
    const float* emb    = (const float*)d_in[2];
    const float* W1_2   = (const float*)d_in[3];
    const float* b1_2   = (const float*)d_in[4];
    const float* W2_2   = (const float*)d_in[5];
    const float* b2_2   = (const float*)d_in[6];
    const float* W1_3   = (const float*)d_in[7];
    const float* b1_3   = (const float*)d_in[8];
    const float* W2_3   = (const float*)d_in[9];
    const float* b2_3   = (const float*)d_in[10];
    const float* keyW   = (const float*)d_in[11];
    const float* keyb   = (const float*)d_in[12];
    const float* valW   = (const float*)d_in[13];
    const float* valb   = (const float*)d_in[14];
    const float* n1g    = (const float*)d_in[15];
    const float* n1b    = (const float*)d_in[16];
    const float* n2g    = (const float*)d_in[17];
    const float* n2b    = (const float*)d_in[18];
    const float* cw     = (const float*)d_in[19];
    const float* cg     = (const float*)d_in[20];
    const float* cb     = (const float*)d_in[21];
    float* out = (float*)d_out;

    precompute_tables<<<500, 256>>>(emb, W1_2, b1_2, W1_3, b1_3);

    const size_t smem = 55296 * sizeof(float);  // 221184 B
    cudaFuncSetAttribute(main_kernel, cudaFuncAttributeMaxDynamicSharedMemorySize,
                         (int)smem);
    main_kernel<<<148, 256, smem>>>(ids, hidden, W2_2, b2_2, W2_3, b2_3,
                                    keyW, keyb, valW, valb,
                                    n1g, n1b, n2g, n2b, cg, cb);

    conv_kernel<<<NTOK * 32 / 256, 256>>>(cw, out);
}

// round 7
// speedup vs baseline: 1.0015x; 1.0015x over previous
#include <cuda_runtime.h>
#include <math.h>
#include <stdint.h>

typedef unsigned long long ull;

// Problem constants
#define BB    32
#define TT    8192
#define NTOK  (BB * TT)      // 262144
#define NGRP  (NTOK / 4)     // 65536 groups of 4 tokens (one warp-pair each)

// ---------------------------------------------------------------------------
// Device-global scratch
// ---------------------------------------------------------------------------
__device__ float g_T2a[500 * 256];
__device__ float g_T2b[500 * 256];
__device__ float g_T3a[500 * 256];
__device__ float g_T3b[500 * 256];
__device__ float g_T3c[500 * 256];
__device__ float g_Val [(size_t)NTOK * 64];   // gated value (residual input)
__device__ float g_ValN[(size_t)NTOK * 64];   // conv-LN(gated value)*g+b

__device__ __forceinline__ float silu_f(float x) {
    return __fdividef(x, 1.0f + __expf(-x));
}
__device__ __forceinline__ float wsum(float v) {
#pragma unroll
    for (int m = 16; m > 0; m >>= 1) v += __shfl_xor_sync(0xffffffffu, v, m);
    return v;
}
__device__ __forceinline__ ull pack2(float lo, float hi) {
    return (ull)__float_as_uint(lo) | ((ull)__float_as_uint(hi) << 32);
}
__device__ __forceinline__ float f2sum(ull v) {
    return __uint_as_float((unsigned)v) + __uint_as_float((unsigned)(v >> 32));
}
// Packed fp32x2 FMA (Blackwell FFMA2; only reachable via PTX)
#define FMA2(acc, a, b) \
    asm("fma.rn.f32x2 %0, %1, %2, %0;" : "+l"(acc) : "l"(a), "l"(b))

#define PBAR() asm volatile("bar.sync %0, 64;" :: "r"(pairid + 1) : "memory")

// ---------------------------------------------------------------------------
// Kernel 1: per-vocab table precompute (unchanged, 20us)
// ---------------------------------------------------------------------------
__global__ void precompute_tables(const float* __restrict__ emb,
                                  const float* __restrict__ W1_2,
                                  const float* __restrict__ b1_2,
                                  const float* __restrict__ W1_3,
                                  const float* __restrict__ b1_3) {
    __shared__ float e[64];
    const int id = blockIdx.x;
    const int o  = threadIdx.x;
    if (o < 64) e[o] = emb[id * 64 + o];
    __syncthreads();

    float a2 = 0.f, b2 = 0.f, a3 = 0.f, b3 = 0.f, c3 = 0.f;
#pragma unroll 8
    for (int d = 0; d < 64; d++) {
        const float ev = e[d];
        a2 += ev * W1_2[d * 256 + o];
        b2 += ev * W1_2[(64 + d) * 256 + o];
        a3 += ev * W1_3[d * 256 + o];
        b3 += ev * W1_3[(64 + d) * 256 + o];
        c3 += ev * W1_3[(128 + d) * 256 + o];
    }
    g_T2a[id * 256 + o] = a2;
    g_T2b[id * 256 + o] = b2 + b1_2[o];
    g_T3a[id * 256 + o] = a3;
    g_T3b[id * 256 + o] = b3;
    g_T3c[id * 256 + o] = c3 + b1_3[o];
}

// ---------------------------------------------------------------------------
// Kernel 2: main fused kernel. 256 threads = 8 warps = 4 warp-pairs.
// A pair processes 4 tokens per iteration; the two warps col-split the GEMMs.
// Dynamic smem (floats):
//   [    0 : 16384)  W2_2 pair-packed  (ull idx: kp*64 + c, kp<128, c<64)
//   [16384 : 32768)  W2_3 pair-packed
//   [32768 : 49152)  key|val pair-packed (ull idx: kp*128 + c, kp<64, c<128)
//   [49152 : 53248)  hb: pair p at +p*1024  (4 tok x 256)   [also kv output]
//   [53248 : 55296)  eb: pair p at +p*512   (4 tok x 128)
// Total 55296 floats = 221184 B.
// ---------------------------------------------------------------------------
__global__ void __launch_bounds__(256, 1)
main_kernel(const int*   __restrict__ ids_g,
            const float* __restrict__ hidden,
            const float* __restrict__ W2_2g, const float* __restrict__ b2_2,
            const float* __restrict__ W2_3g, const float* __restrict__ b2_3,
            const float* __restrict__ keyW,  const float* __restrict__ keyb,
            const float* __restrict__ valW,  const float* __restrict__ valb,
            const float* __restrict__ n1g,   const float* __restrict__ n1b,
            const float* __restrict__ n2g,   const float* __restrict__ n2b,
            const float* __restrict__ cg,    const float* __restrict__ cb) {
    extern __shared__ float sm[];
    ull* W2au = (ull*)sm;
    ull* W2bu = (ull*)(sm + 16384);
    ull* KVu  = (ull*)(sm + 32768);

    const int tid    = threadIdx.x;
    const int wid    = tid >> 5;
    const int lane   = tid & 31;
    const int pairid = wid >> 1;
    const int sub    = wid & 1;

    float* hb  = sm + 49152 + pairid * 1024;
    float* eb  = sm + 53248 + pairid * 512;
    ull*   hbu = (ull*)hb;   // [tok*128 + kp]
    ull*   ebu = (ull*)eb;   // [tok*64  + kp]
    float* kvo = hb;         // kv output reuses hb

    // Stage pair-packed weights: pair (2kp, 2kp+1) of column c -> one u64.
    for (int i = tid; i < 8192; i += 256) {
        const int kp = i >> 6, c = i & 63;
        W2au[i] = pack2(W2_2g[kp * 128 + c], W2_2g[kp * 128 + 64 + c]);
        W2bu[i] = pack2(W2_3g[kp * 128 + c], W2_3g[kp * 128 + 64 + c]);
        const int kp2 = i >> 7, c2 = i & 127;
        float lo, hi;
        if (c2 < 64) { lo = keyW[kp2 * 128 + c2];      hi = keyW[kp2 * 128 + 64 + c2]; }
        else         { lo = valW[kp2 * 128 + c2 - 64]; hi = valW[kp2 * 128 + c2]; }
        KVu[i] = pack2(lo, hi);
    }
    __syncthreads();

    // Per-lane hoisted constants
    const int   c     = sub * 32 + lane;       // GEMM output column
    const float bias2 = b2_2[c];
    const float bias3 = b2_3[c];
    const float* kvbp = sub ? valb : keyb;
    const float kvb0  = kvbp[lane], kvb1 = kvbp[lane + 32];
    const float g1x = n1g[lane], g1y = n1g[lane + 32];
    const float o1x = n1b[lane], o1y = n1b[lane + 32];
    const float g2x = n2g[lane], g2y = n2g[lane + 32];
    const float o2x = n2b[lane], o2y = n2b[lane + 32];
    const float cgx = cg[lane],  cgy = cg[lane + 32];
    const float cbx = cb[lane],  cby = cb[lane + 32];
    const int   o0  = lane * 8;

    for (int grp = blockIdx.x * 4 + pairid; grp < NGRP; grp += gridDim.x * 4) {
        const int t0 = grp * 4;
        const int b  = t0 >> 13;
        const int p0 = t0 & 8191;

        PBAR();  // previous iteration's kvo reads complete

        int idx[6];
#pragma unroll
        for (int j = 0; j < 6; j++) {
            const int pp = p0 + j - 2;
            idx[j] = (pp >= 0) ? ids_g[b * TT + pp] : -1;
        }

        // -------- h2 build: this warp's 2 tokens --------
#pragma unroll
        for (int i = 0; i < 2; i++) {
            const int tok = sub * 2 + i;
            const float* rc = g_T2b + idx[tok + 2] * 256 + o0;
            float4 x0 = *(const float4*)rc;
            float4 x1 = *(const float4*)(rc + 4);
            const int ip = idx[tok + 1];
            if (ip >= 0) {
                const float* rp = g_T2a + ip * 256 + o0;
                const float4 y0 = *(const float4*)rp;
                const float4 y1 = *(const float4*)(rp + 4);
                x0.x += y0.x; x0.y += y0.y; x0.z += y0.z; x0.w += y0.w;
                x1.x += y1.x; x1.y += y1.y; x1.z += y1.z; x1.w += y1.w;
            }
            x0.x = silu_f(x0.x); x0.y = silu_f(x0.y); x0.z = silu_f(x0.z); x0.w = silu_f(x0.w);
            x1.x = silu_f(x1.x); x1.y = silu_f(x1.y); x1.z = silu_f(x1.z); x1.w = silu_f(x1.w);
            *(float4*)(hb + tok * 256 + o0)     = x0;
            *(float4*)(hb + tok * 256 + o0 + 4) = x1;
        }
        PBAR();

        // -------- out2 = silu(h2) @ W2_2 (col-split, all 4 tokens) --------
        {
            ull a0 = 0, a1 = 0, a2 = 0, a3 = 0;
#pragma unroll 8
            for (int kp = 0; kp < 128; kp += 2) {
                const ull wA = W2au[kp * 64 + c];
                const ull wB = W2au[kp * 64 + 64 + c];
                const ulonglong2 h0 = *(const ulonglong2*)(hbu + 0 * 128 + kp);
                const ulonglong2 h1 = *(const ulonglong2*)(hbu + 1 * 128 + kp);
                const ulonglong2 h2 = *(const ulonglong2*)(hbu + 2 * 128 + kp);
                const ulonglong2 h3 = *(const ulonglong2*)(hbu + 3 * 128 + kp);
                FMA2(a0, h0.x, wA); FMA2(a0, h0.y, wB);
                FMA2(a1, h1.x, wA); FMA2(a1, h1.y, wB);
                FMA2(a2, h2.x, wA); FMA2(a2, h2.y, wB);
                FMA2(a3, h3.x, wA); FMA2(a3, h3.y, wB);
            }
            eb[0 * 128 + c] = f2sum(a0) + bias2;
            eb[1 * 128 + c] = f2sum(a1) + bias2;
            eb[2 * 128 + c] = f2sum(a2) + bias2;
            eb[3 * 128 + c] = f2sum(a3) + bias2;
        }
        PBAR();  // hb reads done -> safe to rebuild

        // -------- h3 build --------
#pragma unroll
        for (int i = 0; i < 2; i++) {
            const int tok = sub * 2 + i;
            const float* rc = g_T3c + idx[tok + 2] * 256 + o0;
            float4 x0 = *(const float4*)rc;
            float4 x1 = *(const float4*)(rc + 4);
            const int i1 = idx[tok + 1];
            if (i1 >= 0) {
                const float* rp = g_T3b + i1 * 256 + o0;
                const float4 y0 = *(const float4*)rp;
                const float4 y1 = *(const float4*)(rp + 4);
                x0.x += y0.x; x0.y += y0.y; x0.z += y0.z; x0.w += y0.w;
                x1.x += y1.x; x1.y += y1.y; x1.z += y1.z; x1.w += y1.w;
            }
            const int i2 = idx[tok];
            if (i2 >= 0) {
                const float* rp = g_T3a + i2 * 256 + o0;
                const float4 y0 = *(const float4*)rp;
                const float4 y1 = *(const float4*)(rp + 4);
                x0.x += y0.x; x0.y += y0.y; x0.z += y0.z; x0.w += y0.w;
                x1.x += y1.x; x1.y += y1.y; x1.z += y1.z; x1.w += y1.w;
            }
            x0.x = silu_f(x0.x); x0.y = silu_f(x0.y); x0.z = silu_f(x0.z); x0.w = silu_f(x0.w);
            x1.x = silu_f(x1.x); x1.y = silu_f(x1.y); x1.z = silu_f(x1.z); x1.w = silu_f(x1.w);
            *(float4*)(hb + tok * 256 + o0)     = x0;
            *(float4*)(hb + tok * 256 + o0 + 4) = x1;
        }
        PBAR();

        // -------- out3 = silu(h3) @ W2_3 --------
        {
            ull a0 = 0, a1 = 0, a2 = 0, a3 = 0;
#pragma unroll 8
            for (int kp = 0; kp < 128; kp += 2) {
                const ull wA = W2bu[kp * 64 + c];
                const ull wB = W2bu[kp * 64 + 64 + c];
                const ulonglong2 h0 = *(const ulonglong2*)(hbu + 0 * 128 + kp);
                const ulonglong2 h1 = *(const ulonglong2*)(hbu + 1 * 128 + kp);
                const ulonglong2 h2 = *(const ulonglong2*)(hbu + 2 * 128 + kp);
                const ulonglong2 h3 = *(const ulonglong2*)(hbu + 3 * 128 + kp);
                FMA2(a0, h0.x, wA); FMA2(a0, h0.y, wB);
                FMA2(a1, h1.x, wA); FMA2(a1, h1.y, wB);
                FMA2(a2, h2.x, wA); FMA2(a2, h2.y, wB);
                FMA2(a3, h3.x, wA); FMA2(a3, h3.y, wB);
            }
            eb[0 * 128 + 64 + c] = f2sum(a0) + bias3;
            eb[1 * 128 + 64 + c] = f2sum(a1) + bias3;
            eb[2 * 128 + 64 + c] = f2sum(a2) + bias3;
            eb[3 * 128 + 64 + c] = f2sum(a3) + bias3;
        }
        PBAR();  // eb fully written by both warps; hb reads done

        // -------- k/v = emb @ [keyW|valW]; warp covers 64 of 128 out cols ---
        {
            const int ck = sub * 64 + lane;   // cols ck, ck+32
            ull a0 = 0, a1 = 0, a2 = 0, a3 = 0;   // col ck,   tok 0..3
            ull b0 = 0, b1 = 0, b2 = 0, b3 = 0;   // col ck+32
#pragma unroll 4
            for (int kp = 0; kp < 64; kp += 2) {
                const ull w0A = KVu[kp * 128 + ck];
                const ull w0B = KVu[kp * 128 + 128 + ck];
                const ull w1A = KVu[kp * 128 + 32 + ck];
                const ull w1B = KVu[kp * 128 + 160 + ck];
                const ulonglong2 e0 = *(const ulonglong2*)(ebu + 0 * 64 + kp);
                const ulonglong2 e1 = *(const ulonglong2*)(ebu + 1 * 64 + kp);
                const ulonglong2 e2 = *(const ulonglong2*)(ebu + 2 * 64 + kp);
                const ulonglong2 e3 = *(const ulonglong2*)(ebu + 3 * 64 + kp);
                FMA2(a0, e0.x, w0A); FMA2(a0, e0.y, w0B);
                FMA2(b0, e0.x, w1A); FMA2(b0, e0.y, w1B);
                FMA2(a1, e1.x, w0A); FMA2(a1, e1.y, w0B);
                FMA2(b1, e1.x, w1A); FMA2(b1, e1.y, w1B);
                FMA2(a2, e2.x, w0A); FMA2(a2, e2.y, w0B);
                FMA2(b2, e2.x, w1A); FMA2(b2, e2.y, w1B);
                FMA2(a3, e3.x, w0A); FMA2(a3, e3.y, w0B);
                FMA2(b3, e3.x, w1A); FMA2(b3, e3.y, w1B);
            }
            kvo[0 * 128 + ck]      = f2sum(a0) + kvb0;
            kvo[1 * 128 + ck]      = f2sum(a1) + kvb0;
            kvo[2 * 128 + ck]      = f2sum(a2) + kvb0;
            kvo[3 * 128 + ck]      = f2sum(a3) + kvb0;
            kvo[0 * 128 + ck + 32] = f2sum(b0) + kvb1;
            kvo[1 * 128 + ck + 32] = f2sum(b1) + kvb1;
            kvo[2 * 128 + ck + 32] = f2sum(b2) + kvb1;
            kvo[3 * 128 + ck + 32] = f2sum(b3) + kvb1;
        }
        PBAR();

        // -------- epilogue: LN(k), LN(hidden), gate, value, conv-LN --------
#pragma unroll
        for (int i = 0; i < 2; i++) {
            const int tok = sub * 2 + i;
            const float kd0 = kvo[tok * 128 + lane];
            const float kd1 = kvo[tok * 128 + 32 + lane];
            const float vd0 = kvo[tok * 128 + 64 + lane];
            const float vd1 = kvo[tok * 128 + 96 + lane];

            const float mk = wsum(kd0 + kd1) * (1.0f / 64.0f);
            const float qk = wsum(kd0 * kd0 + kd1 * kd1) * (1.0f / 64.0f);
            const float ik = rsqrtf(qk - mk * mk + 1e-5f);
            const float nk0 = (kd0 - mk) * ik * g1x + o1x;
            const float nk1 = (kd1 - mk) * ik * g1y + o1y;

            const float* hr = hidden + ((size_t)(t0 + tok)) * 64;
            const float hq0 = hr[lane];
            const float hq1 = hr[lane + 32];
            const float mh = wsum(hq0 + hq1) * (1.0f / 64.0f);
            const float qh = wsum(hq0 * hq0 + hq1 * hq1) * (1.0f / 64.0f);
            const float ih = rsqrtf(qh - mh * mh + 1e-5f);
            const float nq0 = (hq0 - mh) * ih * g2x + o2x;
            const float nq1 = (hq1 - mh) * ih * g2y + o2y;

            const float dp = wsum(nk0 * nq0 + nk1 * nq1) * 0.125f;
            const float sq = sqrtf(fmaxf(fabsf(dp), 1e-6f));
            const float gs = (dp > 0.f) ? sq : ((dp < 0.f) ? -sq : 0.f);
            const float gate = __fdividef(1.0f, 1.0f + __expf(-gs));

            const float gv0 = gate * vd0;
            const float gv1 = gate * vd1;
            float* vo = g_Val + ((size_t)(t0 + tok)) * 64;
            vo[lane]      = gv0;
            vo[lane + 32] = gv1;

            const float mv = wsum(gv0 + gv1) * (1.0f / 64.0f);
            const float qv = wsum(gv0 * gv0 + gv1 * gv1) * (1.0f / 64.0f);
            const float iv = rsqrtf(qv - mv * mv + 1e-5f);
            float* vn = g_ValN + ((size_t)(t0 + tok)) * 64;
            vn[lane]      = (gv0 - mv) * iv * cgx + cbx;
            vn[lane + 32] = (gv1 - mv) * iv * cgy + cby;
        }
    }
}

// ---------------------------------------------------------------------------
// Kernel 3: streaming causal dilated depthwise conv (LN precomputed).
// Thread = (token, dim-pair). out = Val[t] + silu(sum_j w[d,j]*ValN[t-9+3j,d])
// ---------------------------------------------------------------------------
__global__ void conv_kernel(const float* __restrict__ cw,
                            float* __restrict__ out) {
    const int g     = blockIdx.x * blockDim.x + threadIdx.x;
    const int token = g >> 5;
    const int d0    = (g & 31) * 2;
    const int p     = token & 8191;

    const float4 w0 = *(const float4*)(cw + d0 * 4);
    const float4 w1 = *(const float4*)(cw + d0 * 4 + 4);

    float y0 = 0.f, y1 = 0.f;
    const float* basen = g_ValN + (size_t)token * 64 + d0;
#pragma unroll
    for (int j = 0; j < 4; j++) {
        const int tp = p - 9 + 3 * j;
        if (tp >= 0) {
            const float2 v = *(const float2*)(basen + (long)(3 * j - 9) * 64);
            y0 += ((const float*)&w0)[j] * v.x;
            y1 += ((const float*)&w1)[j] * v.y;
        }
    }
    const float2 r = *(const float2*)(g_Val + (size_t)token * 64 + d0);
    const float2 res = make_float2(r.x + silu_f(y0), r.y + silu_f(y1));
    *(float2*)(out + (size_t)token * 64 + d0) = res;
}

// ---------------------------------------------------------------------------
// Host launcher
// ---------------------------------------------------------------------------
extern "C" void kernel_launch(void* const* d_in, const int* in_sizes, int n_in,
                              void* d_out, int out_size) {
    const float* hidden = (const float*)d_in[0];
    const int*   ids    = (const int*)d_in[1];
    const float* emb    = (const float*)d_in[2];
    const float* W1_2   = (const float*)d_in[3];
    const float* b1_2   = (const float*)d_in[4];
    const float* W2_2   = (const float*)d_in[5];
    const float* b2_2   = (const float*)d_in[6];
    const float* W1_3   = (const float*)d_in[7];
    const float* b1_3   = (const float*)d_in[8];
    const float* W2_3   = (const float*)d_in[9];
    const float* b2_3   = (const float*)d_in[10];
    const float* keyW   = (const float*)d_in[11];
    const float* keyb   = (const float*)d_in[12];
    const float* valW   = (const float*)d_in[13];
    const float* valb   = (const float*)d_in[14];
    const float* n1g    = (const float*)d_in[15];
    const float* n1b    = (const float*)d_in[16];
    const float* n2g    = (const float*)d_in[17];
    const float* n2b    = (const float*)d_in[18];
    const float* cw     = (const float*)d_in[19];
    const float* cg     = (const float*)d_in[20];
    const float* cb     = (const float*)d_in[21];
    float* out = (float*)d_out;

    precompute_tables<<<500, 256>>>(emb, W1_2, b1_2, W1_3, b1_3);

    const size_t smem = 55296 * sizeof(float);  // 221184 B
    cudaFuncSetAttribute(main_kernel, cudaFuncAttributeMaxDynamicSharedMemorySize,
                         (int)smem);
    main_kernel<<<148, 256, smem>>>(ids, hidden, W2_2, b2_2, W2_3, b2_3,
                                    keyW, keyb, valW, valb,
                                    n1g, n1b, n2g, n2b, cg, cb);

    conv_kernel<<<NTOK * 32 / 256, 256>>>(cw, out);
}

// round 8
// speedup vs baseline: 2.9702x; 2.9658x over previous
#include <cuda_runtime.h>
#include <cuda_bf16.h>
#include <math.h>
#include <stdint.h>

#define BB    32
#define TT    8192
#define NTOK  (BB * TT)        // 262144
#define NTIL  (NTOK / 16)      // 16384 16-token tiles

// ---------------------------------------------------------------------------
// Device-global scratch
// ---------------------------------------------------------------------------
// Per-vocab tables, row 500 = zeros (causal pad). b1 folded into T2b/T3c.
__device__ float g_T2a[501 * 256];
__device__ float g_T2b[501 * 256];
__device__ float g_T3a[501 * 256];
__device__ float g_T3b[501 * 256];
__device__ float g_T3c[501 * 256];
__device__ float g_Val [(size_t)NTOK * 64];
__device__ float g_ValN[(size_t)NTOK * 64];
// Fragment-ordered bf16 weight images: G1hi,G1lo,G2hi,G2lo,G3hi,G3lo (8192 u32 each)
__device__ uint32_t g_Bimg[49152];
// kv bias with emb-bias folded: kvb[n] = b2cat @ KVW[:,n] + (keyb|valb)[n]
__device__ float g_kvb[128];

__device__ __forceinline__ float silu_f(float x) {
    return __fdividef(x, 1.0f + __expf(-x));
}
__device__ __forceinline__ float qsum(float v) {   // sum over quad (4 lanes)
    v += __shfl_xor_sync(0xffffffffu, v, 1);
    v += __shfl_xor_sync(0xffffffffu, v, 2);
    return v;
}
// hi/lo bf16 split of a float pair -> packed bf16x2 regs
__device__ __forceinline__ void split2(float a, float b, uint32_t& hi, uint32_t& lo) {
    __nv_bfloat162 h = __floats2bfloat162_rn(a, b);
    __nv_bfloat162 l = __floats2bfloat162_rn(a - __low2float(h), b - __high2float(h));
    hi = *(uint32_t*)&h;
    lo = *(uint32_t*)&l;
}
__device__ __forceinline__ void mma16816(float* d, const uint32_t* a,
                                         uint32_t b0, uint32_t b1) {
    asm volatile(
        "mma.sync.aligned.m16n8k16.row.col.f32.bf16.bf16.f32 "
        "{%0,%1,%2,%3}, {%4,%5,%6,%7}, {%8,%9}, {%0,%1,%2,%3};"
        : "+f"(d[0]), "+f"(d[1]), "+f"(d[2]), "+f"(d[3])
        : "r"(a[0]), "r"(a[1]), "r"(a[2]), "r"(a[3]), "r"(b0), "r"(b1));
}

// ---------------------------------------------------------------------------
// Kernel 1: per-vocab tables (row 500 = zeros)
// ---------------------------------------------------------------------------
__global__ void precompute_tables(const float* __restrict__ emb,
                                  const float* __restrict__ W1_2,
                                  const float* __restrict__ b1_2,
                                  const float* __restrict__ W1_3,
                                  const float* __restrict__ b1_3) {
    __shared__ float e[64];
    const int id = blockIdx.x, o = threadIdx.x;
    if (id == 500) {
        g_T2a[id*256+o] = 0.f; g_T2b[id*256+o] = 0.f;
        g_T3a[id*256+o] = 0.f; g_T3b[id*256+o] = 0.f; g_T3c[id*256+o] = 0.f;
        return;
    }
    if (o < 64) e[o] = emb[id * 64 + o];
    __syncthreads();
    float a2=0.f, b2=0.f, a3=0.f, b3=0.f, c3=0.f;
#pragma unroll 8
    for (int d = 0; d < 64; d++) {
        const float ev = e[d];
        a2 += ev * W1_2[d*256 + o];
        b2 += ev * W1_2[(64+d)*256 + o];
        a3 += ev * W1_3[d*256 + o];
        b3 += ev * W1_3[(64+d)*256 + o];
        c3 += ev * W1_3[(128+d)*256 + o];
    }
    g_T2a[id*256+o] = a2;  g_T2b[id*256+o] = b2 + b1_2[o];
    g_T3a[id*256+o] = a3;  g_T3b[id*256+o] = b3;
    g_T3c[id*256+o] = c3 + b1_3[o];
}

// ---------------------------------------------------------------------------
// Kernel 2: build fragment-ordered bf16 hi/lo B images + folded kv bias.
// Image entry index (per gemm): ((kt*NT + nt)*32 + lane)*2 + j,
// value pair = B[k][n], B[k+1][n] with k = kt*16 + (lane&3)*2 + j*8, n = nt*8 + lane>>2.
// ---------------------------------------------------------------------------
__global__ void build_bimg(const float* __restrict__ W2_2,
                           const float* __restrict__ W2_3,
                           const float* __restrict__ keyW,
                           const float* __restrict__ valW,
                           const float* __restrict__ b2_2,
                           const float* __restrict__ b2_3,
                           const float* __restrict__ keyb,
                           const float* __restrict__ valb) {
    const int idx = blockIdx.x * blockDim.x + threadIdx.x;   // < 24576
    const int g = idx / 8192;
    const int r = idx % 8192;
    const int j = r & 1, lane = (r >> 1) & 31, tn = r >> 6;
    const int NT = (g == 2) ? 16 : 8;
    const int kt = tn / NT, nt = tn % NT;
    const int k = kt*16 + (lane & 3)*2 + j*8;
    const int n = nt*8 + (lane >> 2);
    float w0, w1;
    if (g == 0)      { w0 = W2_2[k*64+n];  w1 = W2_2[(k+1)*64+n]; }
    else if (g == 1) { w0 = W2_3[k*64+n];  w1 = W2_3[(k+1)*64+n]; }
    else if (n < 64) { w0 = keyW[k*64+n];  w1 = keyW[(k+1)*64+n]; }
    else             { w0 = valW[k*64+n-64]; w1 = valW[(k+1)*64+n-64]; }
    uint32_t hi, lo;
    split2(w0, w1, hi, lo);
    g_Bimg[g*16384 + r]        = hi;
    g_Bimg[g*16384 + 8192 + r] = lo;

    if (blockIdx.x == 0 && threadIdx.x < 128) {
        const int nn = threadIdx.x;
        float s = (nn < 64) ? keyb[nn] : valb[nn - 64];
        for (int jj = 0; jj < 128; jj++) {
            const float bj = (jj < 64) ? b2_2[jj] : b2_3[jj - 64];
            const float w  = (nn < 64) ? keyW[jj*64 + nn] : valW[jj*64 + nn - 64];
            s += bj * w;
        }
        g_kvb[nn] = s;
    }
}

// ---------------------------------------------------------------------------
// Kernel 3: main fused kernel. 148 CTAs x 256 thr; warp = 16 tokens (m16).
// ---------------------------------------------------------------------------
__global__ void __launch_bounds__(256, 1)
main_kernel(const int*   __restrict__ ids,
            const float* __restrict__ hidden,
            const float* __restrict__ n1g, const float* __restrict__ n1b,
            const float* __restrict__ n2g, const float* __restrict__ n2b,
            const float* __restrict__ cg,  const float* __restrict__ cb) {
    extern __shared__ uint32_t Bs[];   // 49152 u32 = 192 KB
    {
        uint4* d4 = (uint4*)Bs;
        const uint4* s4 = (const uint4*)g_Bimg;
        for (int i = threadIdx.x; i < 12288; i += 256) d4[i] = s4[i];
    }
    __syncthreads();

    const int wid  = threadIdx.x >> 5;
    const int lane = threadIdx.x & 31;
    const int r    = lane >> 2;          // fragment row (0..7)
    const int qc   = (lane & 3) * 2;     // fragment col base (0,2,4,6)
    const int gw   = blockIdx.x * 8 + wid;

    for (int tile = gw; tile < NTIL; tile += 148 * 8) {
        const int t0 = tile * 16;
        const int p0 = t0 & 8191;        // position in batch (tile never crosses batch)

        // token ids for rows r and r+8 (cur, prev1, prev2; 500 = zero row)
        int ic[2], i1[2], i2[2];
        const int pr = p0 + r;
        ic[0] = ids[t0 + r];
        i1[0] = (pr >= 1) ? ids[t0 + r - 1] : 500;
        i2[0] = (pr >= 2) ? ids[t0 + r - 2] : 500;
        ic[1] = ids[t0 + r + 8];
        i1[1] = ids[t0 + r + 7];
        i2[1] = ids[t0 + r + 6];

        float D1[32], D2[32], DK[64];
#pragma unroll
        for (int i = 0; i < 32; i++) { D1[i] = 0.f; D2[i] = 0.f; }
#pragma unroll
        for (int i = 0; i < 64; i++) DK[i] = 0.f;

        // ---------------- GEMM1: D1 = silu(T2 sums) @ W2_2 ----------------
        for (int kt = 0; kt < 16; kt++) {
            uint32_t ah[4], al[4];
            const int cbs = kt * 16 + qc;
#pragma unroll
            for (int h = 0; h < 2; h++) {
                const float* tb = g_T2b + ic[h] * 256 + cbs;
                const float* ta = g_T2a + i1[h] * 256 + cbs;
                const float2 xa = *(const float2*)tb;
                const float2 xb = *(const float2*)(tb + 8);
                const float2 ya = *(const float2*)ta;
                const float2 yb = *(const float2*)(ta + 8);
                split2(silu_f(xa.x + ya.x), silu_f(xa.y + ya.y), ah[h],     al[h]);
                split2(silu_f(xb.x + yb.x), silu_f(xb.y + yb.y), ah[h + 2], al[h + 2]);
            }
#pragma unroll
            for (int nt = 0; nt < 8; nt++) {
                const int e = ((kt * 8 + nt) * 32 + lane) * 2;
                const uint2 bh = *(const uint2*)(Bs + e);
                const uint2 bl = *(const uint2*)(Bs + 8192 + e);
                mma16816(D1 + nt*4, ah, bh.x, bh.y);
                mma16816(D1 + nt*4, al, bh.x, bh.y);
                mma16816(D1 + nt*4, ah, bl.x, bl.y);
            }
        }

        // ---------------- GEMM2: D2 = silu(T3 sums) @ W2_3 ----------------
        for (int kt = 0; kt < 16; kt++) {
            uint32_t ah[4], al[4];
            const int cbs = kt * 16 + qc;
#pragma unroll
            for (int h = 0; h < 2; h++) {
                const float* tc = g_T3c + ic[h] * 256 + cbs;
                const float* tb = g_T3b + i1[h] * 256 + cbs;
                const float* ta = g_T3a + i2[h] * 256 + cbs;
                const float2 xa = *(const float2*)tc;
                const float2 xb = *(const float2*)(tc + 8);
                const float2 ya = *(const float2*)tb;
                const float2 yb = *(const float2*)(tb + 8);
                const float2 za = *(const float2*)ta;
                const float2 zb = *(const float2*)(ta + 8);
                split2(silu_f(xa.x + ya.x + za.x), silu_f(xa.y + ya.y + za.y), ah[h],   al[h]);
                split2(silu_f(xb.x + yb.x + zb.x), silu_f(xb.y + yb.y + zb.y), ah[h+2], al[h+2]);
            }
#pragma unroll
            for (int nt = 0; nt < 8; nt++) {
                const int e = ((kt * 8 + nt) * 32 + lane) * 2;
                const uint2 bh = *(const uint2*)(Bs + 16384 + e);
                const uint2 bl = *(const uint2*)(Bs + 24576 + e);
                mma16816(D2 + nt*4, ah, bh.x, bh.y);
                mma16816(D2 + nt*4, al, bh.x, bh.y);
                mma16816(D2 + nt*4, ah, bl.x, bl.y);
            }
        }

        // ------- GEMM3: DK = emb @ [keyW|valW]; A = repacked D1/D2 -------
#pragma unroll
        for (int kt = 0; kt < 8; kt++) {
            const float* S = (kt < 4) ? D1 : D2;
            const int tb = (kt & 3) * 2;    // D tile pair 2kt, 2kt+1 within source
            uint32_t ah[4], al[4];
            split2(S[tb*4+0],   S[tb*4+1],   ah[0], al[0]);  // row r,   cols 2c..2c+1
            split2(S[tb*4+2],   S[tb*4+3],   ah[1], al[1]);  // row r+8
            split2(S[tb*4+4],   S[tb*4+5],   ah[2], al[2]);  // row r,   cols 2c+8..9
            split2(S[tb*4+6],   S[tb*4+7],   ah[3], al[3]);  // row r+8
#pragma unroll
            for (int nt = 0; nt < 16; nt++) {
                const int e = ((kt * 16 + nt) * 32 + lane) * 2;
                const uint2 bh = *(const uint2*)(Bs + 32768 + e);
                const uint2 bl = *(const uint2*)(Bs + 40960 + e);
                mma16816(DK + nt*4, ah, bh.x, bh.y);
                mma16816(DK + nt*4, al, bh.x, bh.y);
                mma16816(DK + nt*4, ah, bl.x, bl.y);
            }
        }

        // ---------------- epilogue (per half-row) ----------------
#pragma unroll
        for (int h = 0; h < 2; h++) {
            const int t = t0 + r + 8 * h;
            // key with folded bias; LN stats
            float kd[16], s = 0.f, q = 0.f;
#pragma unroll
            for (int nt = 0; nt < 8; nt++) {
                const float2 kb = *(const float2*)(g_kvb + nt*8 + qc);
                const float u0 = DK[nt*4 + 2*h]     + kb.x;
                const float u1 = DK[nt*4 + 2*h + 1] + kb.y;
                kd[nt*2] = u0; kd[nt*2+1] = u1;
                s += u0 + u1;  q += u0*u0 + u1*u1;
            }
            s = qsum(s); q = qsum(q);
            const float mk = s * (1.f/64.f);
            const float ik = rsqrtf(q * (1.f/64.f) - mk*mk + 1e-5f);
            // hidden LN
            float hv[16], hs = 0.f, hq = 0.f;
#pragma unroll
            for (int nt = 0; nt < 8; nt++) {
                const float2 hh = *(const float2*)(hidden + (size_t)t*64 + nt*8 + qc);
                hv[nt*2] = hh.x; hv[nt*2+1] = hh.y;
                hs += hh.x + hh.y;  hq += hh.x*hh.x + hh.y*hh.y;
            }
            hs = qsum(hs); hq = qsum(hq);
            const float mh = hs * (1.f/64.f);
            const float ih = rsqrtf(hq * (1.f/64.f) - mh*mh + 1e-5f);
            // gate dot
            float dp = 0.f;
#pragma unroll
            for (int nt = 0; nt < 8; nt++) {
                const int col = nt*8 + qc;
                const float2 ga = *(const float2*)(n1g + col);
                const float2 ba = *(const float2*)(n1b + col);
                const float2 gb = *(const float2*)(n2g + col);
                const float2 bbv = *(const float2*)(n2b + col);
                const float nk0 = (kd[nt*2]   - mk) * ik * ga.x + ba.x;
                const float nk1 = (kd[nt*2+1] - mk) * ik * ga.y + ba.y;
                const float nq0 = (hv[nt*2]   - mh) * ih * gb.x + bbv.x;
                const float nq1 = (hv[nt*2+1] - mh) * ih * gb.y + bbv.y;
                dp += nk0*nq0 + nk1*nq1;
            }
            dp = qsum(dp) * 0.125f;
            const float sq = sqrtf(fmaxf(fabsf(dp), 1e-6f));
            const float gs = (dp > 0.f) ? sq : ((dp < 0.f) ? -sq : 0.f);
            const float gate = __fdividef(1.f, 1.f + __expf(-gs));
            // gated value + conv LN
            float gv[16], vs = 0.f, vq = 0.f;
#pragma unroll
            for (int nt = 8; nt < 16; nt++) {
                const float2 kb = *(const float2*)(g_kvb + nt*8 + qc);
                const float g0 = gate * (DK[nt*4 + 2*h]     + kb.x);
                const float g1 = gate * (DK[nt*4 + 2*h + 1] + kb.y);
                gv[(nt-8)*2] = g0; gv[(nt-8)*2+1] = g1;
                *(float2*)(g_Val + (size_t)t*64 + (nt-8)*8 + qc) = make_float2(g0, g1);
                vs += g0 + g1;  vq += g0*g0 + g1*g1;
            }
            vs = qsum(vs); vq = qsum(vq);
            const float mv = vs * (1.f/64.f);
            const float iv = rsqrtf(vq * (1.f/64.f) - mv*mv + 1e-5f);
#pragma unroll
            for (int nt = 0; nt < 8; nt++) {
                const int col = nt*8 + qc;
                const float2 gc = *(const float2*)(cg + col);
                const float2 bc = *(const float2*)(cb + col);
                *(float2*)(g_ValN + (size_t)t*64 + col) = make_float2(
                    (gv[nt*2]   - mv) * iv * gc.x + bc.x,
                    (gv[nt*2+1] - mv) * iv * gc.y + bc.y);
            }
        }
    }
}

// ---------------------------------------------------------------------------
// Kernel 4: streaming causal dilated depthwise conv (LN precomputed)
// ---------------------------------------------------------------------------
__global__ void conv_kernel(const float* __restrict__ cw,
                            float* __restrict__ out) {
    const int g     = blockIdx.x * blockDim.x + threadIdx.x;
    const int token = g >> 5;
    const int d0    = (g & 31) * 2;
    const int p     = token & 8191;

    const float4 w0 = *(const float4*)(cw + d0 * 4);
    const float4 w1 = *(const float4*)(cw + d0 * 4 + 4);

    float y0 = 0.f, y1 = 0.f;
    const float* basen = g_ValN + (size_t)token * 64 + d0;
#pragma unroll
    for (int j = 0; j < 4; j++) {
        const int tp = p - 9 + 3 * j;
        if (tp >= 0) {
            const float2 v = *(const float2*)(basen + (long)(3 * j - 9) * 64);
            y0 += ((const float*)&w0)[j] * v.x;
            y1 += ((const float*)&w1)[j] * v.y;
        }
    }
    const float2 rr = *(const float2*)(g_Val + (size_t)token * 64 + d0);
    *(float2*)(out + (size_t)token * 64 + d0) =
        make_float2(rr.x + silu_f(y0), rr.y + silu_f(y1));
}

// ---------------------------------------------------------------------------
// Host launcher
// ---------------------------------------------------------------------------
extern "C" void kernel_launch(void* const* d_in, const int* in_sizes, int n_in,
                              void* d_out, int out_size) {
    const float* hidden = (const float*)d_in[0];
    const int*   ids    = (const int*)d_in[1];
    const float* emb    = (const float*)d_in[2];
    const float* W1_2   = (const float*)d_in[3];
    const float* b1_2   = (const float*)d_in[4];
    const float* W2_2   = (const float*)d_in[5];
    const float* b2_2   = (const float*)d_in[6];
    const float* W1_3   = (const float*)d_in[7];
    const float* b1_3   = (const float*)d_in[8];
    const float* W2_3   = (const float*)d_in[9];
    const float* b2_3   = (const float*)d_in[10];
    const float* keyW   = (const float*)d_in[11];
    const float* keyb   = (const float*)d_in[12];
    const float* valW   = (const float*)d_in[13];
    const float* valb   = (const float*)d_in[14];
    const float* n1g    = (const float*)d_in[15];
    const float* n1b    = (const float*)d_in[16];
    const float* n2g    = (const float*)d_in[17];
    const float* n2b    = (const float*)d_in[18];
    const float* cw     = (const float*)d_in[19];
    const float* cg     = (const float*)d_in[20];
    const float* cb     = (const float*)d_in[21];
    float* out = (float*)d_out;

    precompute_tables<<<501, 256>>>(emb, W1_2, b1_2, W1_3, b1_3);
    build_bimg<<<96, 256>>>(W2_2, W2_3, keyW, valW, b2_2, b2_3, keyb, valb);

    const size_t smem = 49152 * sizeof(uint32_t);  // 196608 B
    cudaFuncSetAttribute(main_kernel, cudaFuncAttributeMaxDynamicSharedMemorySize,
                         (int)smem);
    main_kernel<<<148, 256, smem>>>(ids, hidden, n1g, n1b, n2g, n2b, cg, cb);

    conv_kernel<<<NTOK * 32 / 256, 256>>>(cw, out);
}

// round 9
// speedup vs baseline: 2.9975x; 1.0092x over previous
#include <cuda_runtime.h>
#include <cuda_bf16.h>
#include <cuda_fp16.h>
#include <math.h>
#include <stdint.h>

#define BB    32
#define TT    8192
#define NTOK  (BB * TT)        // 262144
#define NTIL  (NTOK / 16)      // 16384 16-token tiles

// ---------------------------------------------------------------------------
// Device-global scratch
// ---------------------------------------------------------------------------
// Per-vocab tables, row 500 = zeros (causal pad). b1 folded into T2b/T3c.
__device__ float g_T2a[501 * 256];
__device__ float g_T2b[501 * 256];
__device__ float g_T3a[501 * 256];
__device__ float g_T3b[501 * 256];
__device__ float g_T3c[501 * 256];
__device__ float  g_Val [(size_t)NTOK * 64];
__device__ __half g_ValN[(size_t)NTOK * 64];
// Fused fragment images: per mma-tile, per lane, uint4 {hi0, hi1, lo0, lo1}.
// G1: tiles 0..127 @ base 0; G2: @ 4096 uint4; G3: @ 8192 uint4.
__device__ uint4 g_Bimg[12288];
// kv bias with emb-bias folded: kvb[n] = b2cat @ KVW[:,n] + (keyb|valb)[n]
__device__ float g_kvb[128];

__device__ __forceinline__ float silu_f(float x) {
    return __fdividef(x, 1.0f + __expf(-x));
}
__device__ __forceinline__ float qsum(float v) {   // sum over quad (4 lanes)
    v += __shfl_xor_sync(0xffffffffu, v, 1);
    v += __shfl_xor_sync(0xffffffffu, v, 2);
    return v;
}
// hi/lo bf16 split of a float pair -> packed bf16x2 regs
__device__ __forceinline__ void split2(float a, float b, uint32_t& hi, uint32_t& lo) {
    __nv_bfloat162 h = __floats2bfloat162_rn(a, b);
    __nv_bfloat162 l = __floats2bfloat162_rn(a - __low2float(h), b - __high2float(h));
    hi = *(uint32_t*)&h;
    lo = *(uint32_t*)&l;
}
__device__ __forceinline__ void mma16816(float* d, const uint32_t* a,
                                         uint32_t b0, uint32_t b1) {
    asm volatile(
        "mma.sync.aligned.m16n8k16.row.col.f32.bf16.bf16.f32 "
        "{%0,%1,%2,%3}, {%4,%5,%6,%7}, {%8,%9}, {%0,%1,%2,%3};"
        : "+f"(d[0]), "+f"(d[1]), "+f"(d[2]), "+f"(d[3])
        : "r"(a[0]), "r"(a[1]), "r"(a[2]), "r"(a[3]), "r"(b0), "r"(b1));
}

// ---------------------------------------------------------------------------
// Kernel 1: per-vocab tables (row 500 = zeros)
// ---------------------------------------------------------------------------
__global__ void precompute_tables(const float* __restrict__ emb,
                                  const float* __restrict__ W1_2,
                                  const float* __restrict__ b1_2,
                                  const float* __restrict__ W1_3,
                                  const float* __restrict__ b1_3) {
    __shared__ float e[64];
    const int id = blockIdx.x, o = threadIdx.x;
    if (id == 500) {
        g_T2a[id*256+o] = 0.f; g_T2b[id*256+o] = 0.f;
        g_T3a[id*256+o] = 0.f; g_T3b[id*256+o] = 0.f; g_T3c[id*256+o] = 0.f;
        return;
    }
    if (o < 64) e[o] = emb[id * 64 + o];
    __syncthreads();
    float a2=0.f, b2=0.f, a3=0.f, b3=0.f, c3=0.f;
#pragma unroll 8
    for (int d = 0; d < 64; d++) {
        const float ev = e[d];
        a2 += ev * W1_2[d*256 + o];
        b2 += ev * W1_2[(64+d)*256 + o];
        a3 += ev * W1_3[d*256 + o];
        b3 += ev * W1_3[(64+d)*256 + o];
        c3 += ev * W1_3[(128+d)*256 + o];
    }
    g_T2a[id*256+o] = a2;  g_T2b[id*256+o] = b2 + b1_2[o];
    g_T3a[id*256+o] = a3;  g_T3b[id*256+o] = b3;
    g_T3c[id*256+o] = c3 + b1_3[o];
}

// ---------------------------------------------------------------------------
// Kernel 2: fused-fragment B images + folded kv bias.
// Thread idx < 12288 = g*4096 + tile*32 + lane.
// k0 = kt*16 + (lane&3)*2 ; n = nt*8 + lane>>2.
// uint4 = { hi(k0,k0+1), hi(k0+8,k0+9), lo(k0,k0+1), lo(k0+8,k0+9) }.
// ---------------------------------------------------------------------------
__global__ void build_bimg(const float* __restrict__ W2_2,
                           const float* __restrict__ W2_3,
                           const float* __restrict__ keyW,
                           const float* __restrict__ valW,
                           const float* __restrict__ b2_2,
                           const float* __restrict__ b2_3,
                           const float* __restrict__ keyb,
                           const float* __restrict__ valb) {
    const int idx = blockIdx.x * blockDim.x + threadIdx.x;
    if (idx < 12288) {
        const int g    = idx >> 12;
        const int tile = (idx >> 5) & 127;
        const int lane = idx & 31;
        const int NT = (g == 2) ? 16 : 8;
        const int kt = tile / NT, nt = tile % NT;
        const int k0 = kt*16 + (lane & 3)*2;
        const int n  = nt*8 + (lane >> 2);
        float w00, w01, w10, w11;
        if (g == 0) {
            w00 = W2_2[k0*64+n];      w01 = W2_2[(k0+1)*64+n];
            w10 = W2_2[(k0+8)*64+n];  w11 = W2_2[(k0+9)*64+n];
        } else if (g == 1) {
            w00 = W2_3[k0*64+n];      w01 = W2_3[(k0+1)*64+n];
            w10 = W2_3[(k0+8)*64+n];  w11 = W2_3[(k0+9)*64+n];
        } else if (n < 64) {
            w00 = keyW[k0*64+n];      w01 = keyW[(k0+1)*64+n];
            w10 = keyW[(k0+8)*64+n];  w11 = keyW[(k0+9)*64+n];
        } else {
            w00 = valW[k0*64+n-64];     w01 = valW[(k0+1)*64+n-64];
            w10 = valW[(k0+8)*64+n-64]; w11 = valW[(k0+9)*64+n-64];
        }
        uint4 q;
        split2(w00, w01, q.x, q.z);
        split2(w10, w11, q.y, q.w);
        g_Bimg[idx] = q;
    }
    if (blockIdx.x == 0 && threadIdx.x < 128) {
        const int nn = threadIdx.x;
        float s = (nn < 64) ? keyb[nn] : valb[nn - 64];
        for (int jj = 0; jj < 128; jj++) {
            const float bj = (jj < 64) ? b2_2[jj] : b2_3[jj - 64];
            const float w  = (nn < 64) ? keyW[jj*64 + nn] : valW[jj*64 + nn - 64];
            s += bj * w;
        }
        g_kvb[nn] = s;
    }
}

// ---------------------------------------------------------------------------
// Kernel 3: main fused kernel. 148 CTAs x 512 thr (16 warps); warp = 16 tokens.
// ---------------------------------------------------------------------------
__global__ void __launch_bounds__(512, 1)
main_kernel(const int*   __restrict__ ids,
            const float* __restrict__ hidden,
            const float* __restrict__ n1g, const float* __restrict__ n1b,
            const float* __restrict__ n2g, const float* __restrict__ n2b,
            const float* __restrict__ cg,  const float* __restrict__ cb) {
    extern __shared__ uint4 Bs4[];   // 12288 uint4 = 192 KB
    for (int i = threadIdx.x; i < 12288; i += 512) Bs4[i] = g_Bimg[i];
    __syncthreads();

    const int wid  = threadIdx.x >> 5;
    const int lane = threadIdx.x & 31;
    const int r    = lane >> 2;          // fragment row (0..7)
    const int qc   = (lane & 3) * 2;     // fragment col base (0,2,4,6)
    const int gw   = blockIdx.x * 16 + wid;

    for (int tile = gw; tile < NTIL; tile += 148 * 16) {
        const int t0 = tile * 16;
        const int p0 = t0 & 8191;        // tile never crosses batch boundary

        int ic[2], i1[2], i2[2];
        const int pr = p0 + r;
        ic[0] = ids[t0 + r];
        i1[0] = (pr >= 1) ? ids[t0 + r - 1] : 500;
        i2[0] = (pr >= 2) ? ids[t0 + r - 2] : 500;
        ic[1] = ids[t0 + r + 8];
        i1[1] = ids[t0 + r + 7];
        i2[1] = ids[t0 + r + 6];

        float D1[32], D2[32], DK[64];
#pragma unroll
        for (int i = 0; i < 32; i++) { D1[i] = 0.f; D2[i] = 0.f; }
#pragma unroll
        for (int i = 0; i < 64; i++) DK[i] = 0.f;

        // ---------------- GEMM1: D1 = silu(T2 sums) @ W2_2 ----------------
        for (int kt = 0; kt < 16; kt++) {
            uint32_t ah[4], al[4];
            const int cbs = kt * 16 + qc;
#pragma unroll
            for (int h = 0; h < 2; h++) {
                const float* tb = g_T2b + ic[h] * 256 + cbs;
                const float* ta = g_T2a + i1[h] * 256 + cbs;
                const float2 xa = *(const float2*)tb;
                const float2 xb = *(const float2*)(tb + 8);
                const float2 ya = *(const float2*)ta;
                const float2 yb = *(const float2*)(ta + 8);
                split2(silu_f(xa.x + ya.x), silu_f(xa.y + ya.y), ah[h],     al[h]);
                split2(silu_f(xb.x + yb.x), silu_f(xb.y + yb.y), ah[h + 2], al[h + 2]);
            }
#pragma unroll
            for (int nt = 0; nt < 8; nt++) {
                const uint4 q = Bs4[(kt * 8 + nt) * 32 + lane];
                mma16816(D1 + nt*4, ah, q.x, q.y);
                mma16816(D1 + nt*4, al, q.x, q.y);
                mma16816(D1 + nt*4, ah, q.z, q.w);
            }
        }

        // ---------------- GEMM2: D2 = silu(T3 sums) @ W2_3 ----------------
        for (int kt = 0; kt < 16; kt++) {
            uint32_t ah[4], al[4];
            const int cbs = kt * 16 + qc;
#pragma unroll
            for (int h = 0; h < 2; h++) {
                const float* tc = g_T3c + ic[h] * 256 + cbs;
                const float* tb = g_T3b + i1[h] * 256 + cbs;
                const float* ta = g_T3a + i2[h] * 256 + cbs;
                const float2 xa = *(const float2*)tc;
                const float2 xb = *(const float2*)(tc + 8);
                const float2 ya = *(const float2*)tb;
                const float2 yb = *(const float2*)(tb + 8);
                const float2 za = *(const float2*)ta;
                const float2 zb = *(const float2*)(ta + 8);
                split2(silu_f(xa.x + ya.x + za.x), silu_f(xa.y + ya.y + za.y), ah[h],   al[h]);
                split2(silu_f(xb.x + yb.x + zb.x), silu_f(xb.y + yb.y + zb.y), ah[h+2], al[h+2]);
            }
#pragma unroll
            for (int nt = 0; nt < 8; nt++) {
                const uint4 q = Bs4[4096 + (kt * 8 + nt) * 32 + lane];
                mma16816(D2 + nt*4, ah, q.x, q.y);
                mma16816(D2 + nt*4, al, q.x, q.y);
                mma16816(D2 + nt*4, ah, q.z, q.w);
            }
        }

        // ------- GEMM3: DK = emb @ [keyW|valW]; A = repacked D1/D2 -------
#pragma unroll
        for (int kt = 0; kt < 8; kt++) {
            const float* S = (kt < 4) ? D1 : D2;
            const int tb = (kt & 3) * 2;
            uint32_t ah[4], al[4];
            split2(S[tb*4+0], S[tb*4+1], ah[0], al[0]);
            split2(S[tb*4+2], S[tb*4+3], ah[1], al[1]);
            split2(S[tb*4+4], S[tb*4+5], ah[2], al[2]);
            split2(S[tb*4+6], S[tb*4+7], ah[3], al[3]);
#pragma unroll
            for (int nt = 0; nt < 16; nt++) {
                const uint4 q = Bs4[8192 + (kt * 16 + nt) * 32 + lane];
                mma16816(DK + nt*4, ah, q.x, q.y);
                mma16816(DK + nt*4, al, q.x, q.y);
                mma16816(DK + nt*4, ah, q.z, q.w);
            }
        }

        // ---------------- epilogue (per half-row) ----------------
#pragma unroll
        for (int h = 0; h < 2; h++) {
            const int t = t0 + r + 8 * h;
            float kd[16], s = 0.f, q = 0.f;
#pragma unroll
            for (int nt = 0; nt < 8; nt++) {
                const float2 kb = *(const float2*)(g_kvb + nt*8 + qc);
                const float u0 = DK[nt*4 + 2*h]     + kb.x;
                const float u1 = DK[nt*4 + 2*h + 1] + kb.y;
                kd[nt*2] = u0; kd[nt*2+1] = u1;
                s += u0 + u1;  q += u0*u0 + u1*u1;
            }
            s = qsum(s); q = qsum(q);
            const float mk = s * (1.f/64.f);
            const float ik = rsqrtf(q * (1.f/64.f) - mk*mk + 1e-5f);
            float hv[16], hs = 0.f, hq = 0.f;
#pragma unroll
            for (int nt = 0; nt < 8; nt++) {
                const float2 hh = *(const float2*)(hidden + (size_t)t*64 + nt*8 + qc);
                hv[nt*2] = hh.x; hv[nt*2+1] = hh.y;
                hs += hh.x + hh.y;  hq += hh.x*hh.x + hh.y*hh.y;
            }
            hs = qsum(hs); hq = qsum(hq);
            const float mh = hs * (1.f/64.f);
            const float ih = rsqrtf(hq * (1.f/64.f) - mh*mh + 1e-5f);
            float dp = 0.f;
#pragma unroll
            for (int nt = 0; nt < 8; nt++) {
                const int col = nt*8 + qc;
                const float2 ga = *(const float2*)(n1g + col);
                const float2 ba = *(const float2*)(n1b + col);
                const float2 gb = *(const float2*)(n2g + col);
                const float2 bbv = *(const float2*)(n2b + col);
                const float nk0 = (kd[nt*2]   - mk) * ik * ga.x + ba.x;
                const float nk1 = (kd[nt*2+1] - mk) * ik * ga.y + ba.y;
                const float nq0 = (hv[nt*2]   - mh) * ih * gb.x + bbv.x;
                const float nq1 = (hv[nt*2+1] - mh) * ih * gb.y + bbv.y;
                dp += nk0*nq0 + nk1*nq1;
            }
            dp = qsum(dp) * 0.125f;
            const float sq = sqrtf(fmaxf(fabsf(dp), 1e-6f));
            const float gs = (dp > 0.f) ? sq : ((dp < 0.f) ? -sq : 0.f);
            const float gate = __fdividef(1.f, 1.f + __expf(-gs));
            float gv[16], vs = 0.f, vq = 0.f;
#pragma unroll
            for (int nt = 8; nt < 16; nt++) {
                const float2 kb = *(const float2*)(g_kvb + nt*8 + qc);
                const float g0 = gate * (DK[nt*4 + 2*h]     + kb.x);
                const float g1 = gate * (DK[nt*4 + 2*h + 1] + kb.y);
                gv[(nt-8)*2] = g0; gv[(nt-8)*2+1] = g1;
                *(float2*)(g_Val + (size_t)t*64 + (nt-8)*8 + qc) = make_float2(g0, g1);
                vs += g0 + g1;  vq += g0*g0 + g1*g1;
            }
            vs = qsum(vs); vq = qsum(vq);
            const float mv = vs * (1.f/64.f);
            const float iv = rsqrtf(vq * (1.f/64.f) - mv*mv + 1e-5f);
#pragma unroll
            for (int nt = 0; nt < 8; nt++) {
                const int col = nt*8 + qc;
                const float2 gc = *(const float2*)(cg + col);
                const float2 bc = *(const float2*)(cb + col);
                const float v0 = (gv[nt*2]   - mv) * iv * gc.x + bc.x;
                const float v1 = (gv[nt*2+1] - mv) * iv * gc.y + bc.y;
                *(__half2*)(g_ValN + (size_t)t*64 + col) = __floats2half2_rn(v0, v1);
            }
        }
    }
}

// ---------------------------------------------------------------------------
// Kernel 4: streaming causal dilated depthwise conv (fp16 LN'd taps)
// ---------------------------------------------------------------------------
__global__ void conv_kernel(const float* __restrict__ cw,
                            float* __restrict__ out) {
    const int g     = blockIdx.x * blockDim.x + threadIdx.x;
    const int token = g >> 5;
    const int d0    = (g & 31) * 2;
    const int p     = token & 8191;

    const float4 w0 = *(const float4*)(cw + d0 * 4);
    const float4 w1 = *(const float4*)(cw + d0 * 4 + 4);

    float y0 = 0.f, y1 = 0.f;
    const __half* basen = g_ValN + (size_t)token * 64 + d0;
#pragma unroll
    for (int j = 0; j < 4; j++) {
        const int tp = p - 9 + 3 * j;
        if (tp >= 0) {
            const __half2 vh = *(const __half2*)(basen + (long)(3 * j - 9) * 64);
            const float2 v = __half22float2(vh);
            y0 += ((const float*)&w0)[j] * v.x;
            y1 += ((const float*)&w1)[j] * v.y;
        }
    }
    const float2 rr = __ldcs((const float2*)(g_Val + (size_t)token * 64 + d0));
    __stcs((float2*)(out + (size_t)token * 64 + d0),
           make_float2(rr.x + silu_f(y0), rr.y + silu_f(y1)));
}

// ---------------------------------------------------------------------------
// Host launcher
// ---------------------------------------------------------------------------
extern "C" void kernel_launch(void* const* d_in, const int* in_sizes, int n_in,
                              void* d_out, int out_size) {
    const float* hidden = (const float*)d_in[0];
    const int*   ids    = (const int*)d_in[1];
    const float* emb    = (const float*)d_in[2];
    const float* W1_2   = (const float*)d_in[3];
    const float* b1_2   = (const float*)d_in[4];
    const float* W2_2   = (const float*)d_in[5];
    const float* b2_2   = (const float*)d_in[6];
    const float* W1_3   = (const float*)d_in[7];
    const float* b1_3   = (const float*)d_in[8];
    const float* W2_3   = (const float*)d_in[9];
    const float* b2_3   = (const float*)d_in[10];
    const float* keyW   = (const float*)d_in[11];
    const float* keyb   = (const float*)d_in[12];
    const float* valW   = (const float*)d_in[13];
    const float* valb   = (const float*)d_in[14];
    const float* n1g    = (const float*)d_in[15];
    const float* n1b    = (const float*)d_in[16];
    const float* n2g    = (const float*)d_in[17];
    const float* n2b    = (const float*)d_in[18];
    const float* cw     = (const float*)d_in[19];
    const float* cg     = (const float*)d_in[20];
    const float* cb     = (const float*)d_in[21];
    float* out = (float*)d_out;

    precompute_tables<<<501, 256>>>(emb, W1_2, b1_2, W1_3, b1_3);
    build_bimg<<<48, 256>>>(W2_2, W2_3, keyW, valW, b2_2, b2_3, keyb, valb);

    const size_t smem = 12288 * sizeof(uint4);  // 196608 B
    cudaFuncSetAttribute(main_kernel, cudaFuncAttributeMaxDynamicSharedMemorySize,
                         (int)smem);
    main_kernel<<<148, 512, smem>>>(ids, hidden, n1g, n1b, n2g, n2b, cg, cb);

    conv_kernel<<<NTOK * 32 / 256, 256>>>(cw, out);
}

// round 10
// speedup vs baseline: 3.2192x; 1.0740x over previous
#include <cuda_runtime.h>
#include <cuda_bf16.h>
#include <cuda_fp16.h>
#include <math.h>
#include <stdint.h>

#define BB    32
#define TT    8192
#define NTOK  (BB * TT)        // 262144
#define NTIL  (NTOK / 16)      // 16384 16-token tiles

// ---------------------------------------------------------------------------
// Device-global scratch
// ---------------------------------------------------------------------------
// Per-vocab tables, row 500 = zeros (causal pad). b1 folded into T2b/T3c.
__device__ float g_T2a[501 * 256];
__device__ float g_T2b[501 * 256];
__device__ float g_T3a[501 * 256];
__device__ float g_T3b[501 * 256];
__device__ float g_T3c[501 * 256];
__device__ float  g_Val [(size_t)NTOK * 64];
__device__ __half g_ValN[(size_t)NTOK * 64];
// Fused fragment images: per mma-tile, per lane, uint4 {hi0, hi1, lo0, lo1}.
// G1: tiles 0..127 @ 0; G2: @ 4096 uint4; G3: @ 8192 uint4.
// G1/G2 use the k-permuted layout (A loads its own float4); G3 is standard.
__device__ uint4 g_Bimg[12288];
// kv bias with emb-bias folded: kvb[n] = b2cat @ KVW[:,n] + (keyb|valb)[n]
__device__ float g_kvb[128];

__device__ __forceinline__ float silu_f(float x) {
    return __fdividef(x, 1.0f + __expf(-x));
}
__device__ __forceinline__ float qsum(float v) {   // sum over quad (4 lanes)
    v += __shfl_xor_sync(0xffffffffu, v, 1);
    v += __shfl_xor_sync(0xffffffffu, v, 2);
    return v;
}
// hi/lo bf16 split of a float pair -> packed bf16x2 regs
__device__ __forceinline__ void split2(float a, float b, uint32_t& hi, uint32_t& lo) {
    __nv_bfloat162 h = __floats2bfloat162_rn(a, b);
    __nv_bfloat162 l = __floats2bfloat162_rn(a - __low2float(h), b - __high2float(h));
    hi = *(uint32_t*)&h;
    lo = *(uint32_t*)&l;
}
__device__ __forceinline__ void mma16816(float* d, const uint32_t* a,
                                         uint32_t b0, uint32_t b1) {
    asm volatile(
        "mma.sync.aligned.m16n8k16.row.col.f32.bf16.bf16.f32 "
        "{%0,%1,%2,%3}, {%4,%5,%6,%7}, {%8,%9}, {%0,%1,%2,%3};"
        : "+f"(d[0]), "+f"(d[1]), "+f"(d[2]), "+f"(d[3])
        : "r"(a[0]), "r"(a[1]), "r"(a[2]), "r"(a[3]), "r"(b0), "r"(b1));
}

// ---------------------------------------------------------------------------
// Kernel 1: per-vocab tables (row 500 = zeros)
// ---------------------------------------------------------------------------
__global__ void precompute_tables(const float* __restrict__ emb,
                                  const float* __restrict__ W1_2,
                                  const float* __restrict__ b1_2,
                                  const float* __restrict__ W1_3,
                                  const float* __restrict__ b1_3) {
    __shared__ float e[64];
    const int id = blockIdx.x, o = threadIdx.x;
    if (id == 500) {
        g_T2a[id*256+o] = 0.f; g_T2b[id*256+o] = 0.f;
        g_T3a[id*256+o] = 0.f; g_T3b[id*256+o] = 0.f; g_T3c[id*256+o] = 0.f;
        return;
    }
    if (o < 64) e[o] = emb[id * 64 + o];
    __syncthreads();
    float a2=0.f, b2=0.f, a3=0.f, b3=0.f, c3=0.f;
#pragma unroll 8
    for (int d = 0; d < 64; d++) {
        const float ev = e[d];
        a2 += ev * W1_2[d*256 + o];
        b2 += ev * W1_2[(64+d)*256 + o];
        a3 += ev * W1_3[d*256 + o];
        b3 += ev * W1_3[(64+d)*256 + o];
        c3 += ev * W1_3[(128+d)*256 + o];
    }
    g_T2a[id*256+o] = a2;  g_T2b[id*256+o] = b2 + b1_2[o];
    g_T3a[id*256+o] = a3;  g_T3b[id*256+o] = b3;
    g_T3c[id*256+o] = c3 + b1_3[o];
}

// ---------------------------------------------------------------------------
// Kernel 2: fused-fragment B images + folded kv bias.
// G1/G2 (g<2): k-PERMUTED so A-fragments come from contiguous float4 loads:
//   fragment k-slot (2q,2q+1)   <- W rows kt*16+4q, +4q+1
//   fragment k-slot (2q+8,2q+9) <- W rows kt*16+4q+2, +4q+3
// G3 (g==2): standard layout: slots (2q,2q+1) and (2q+8,2q+9) <- same k rows.
// uint4 = { hi(b0 pair), hi(b1 pair), lo(b0 pair), lo(b1 pair) }.
// ---------------------------------------------------------------------------
__global__ void build_bimg(const float* __restrict__ W2_2,
                           const float* __restrict__ W2_3,
                           const float* __restrict__ keyW,
                           const float* __restrict__ valW,
                           const float* __restrict__ b2_2,
                           const float* __restrict__ b2_3,
                           const float* __restrict__ keyb,
                           const float* __restrict__ valb) {
    const int idx = blockIdx.x * blockDim.x + threadIdx.x;
    if (idx < 12288) {
        const int g    = idx >> 12;
        const int tile = (idx >> 5) & 127;
        const int lane = idx & 31;
        const int NT = (g == 2) ? 16 : 8;
        const int kt = tile / NT, nt = tile % NT;
        const int n  = nt*8 + (lane >> 2);
        int ka, kb, kc, kd;
        if (g < 2) {   // permuted: contiguous quad
            const int k0 = kt*16 + (lane & 3)*4;
            ka = k0; kb = k0+1; kc = k0+2; kd = k0+3;
        } else {       // standard
            const int k0 = kt*16 + (lane & 3)*2;
            ka = k0; kb = k0+1; kc = k0+8; kd = k0+9;
        }
        float w00, w01, w10, w11;
        if (g == 0) {
            w00 = W2_2[ka*64+n]; w01 = W2_2[kb*64+n];
            w10 = W2_2[kc*64+n]; w11 = W2_2[kd*64+n];
        } else if (g == 1) {
            w00 = W2_3[ka*64+n]; w01 = W2_3[kb*64+n];
            w10 = W2_3[kc*64+n]; w11 = W2_3[kd*64+n];
        } else if (n < 64) {
            w00 = keyW[ka*64+n]; w01 = keyW[kb*64+n];
            w10 = keyW[kc*64+n]; w11 = keyW[kd*64+n];
        } else {
            w00 = valW[ka*64+n-64]; w01 = valW[kb*64+n-64];
            w10 = valW[kc*64+n-64]; w11 = valW[kd*64+n-64];
        }
        uint4 q;
        split2(w00, w01, q.x, q.z);
        split2(w10, w11, q.y, q.w);
        g_Bimg[idx] = q;
    }
    if (blockIdx.x == 0 && threadIdx.x < 128) {
        const int nn = threadIdx.x;
        float s = (nn < 64) ? keyb[nn] : valb[nn - 64];
        for (int jj = 0; jj < 128; jj++) {
            const float bj = (jj < 64) ? b2_2[jj] : b2_3[jj - 64];
            const float w  = (nn < 64) ? keyW[jj*64 + nn] : valW[jj*64 + nn - 64];
            s += bj * w;
        }
        g_kvb[nn] = s;
    }
}

// ---------------------------------------------------------------------------
// Kernel 3: main fused kernel. 148 CTAs x 512 thr (16 warps); warp = 16 tokens.
// ---------------------------------------------------------------------------
__global__ void __launch_bounds__(512, 1)
main_kernel(const int*   __restrict__ ids,
            const float* __restrict__ hidden,
            const float* __restrict__ n1g, const float* __restrict__ n1b,
            const float* __restrict__ n2g, const float* __restrict__ n2b,
            const float* __restrict__ cg,  const float* __restrict__ cb) {
    extern __shared__ uint4 Bs4[];   // 12288 uint4 = 192 KB
    for (int i = threadIdx.x; i < 12288; i += 512) Bs4[i] = g_Bimg[i];
    __syncthreads();

    const int wid  = threadIdx.x >> 5;
    const int lane = threadIdx.x & 31;
    const int r    = lane >> 2;          // fragment row (0..7)
    const int qc   = (lane & 3) * 2;     // fragment col base (0,2,4,6)
    const int qq   = (lane & 3) * 4;     // permuted-gather col base (0,4,8,12)
    const int gw   = blockIdx.x * 16 + wid;

    for (int tile = gw; tile < NTIL; tile += 148 * 16) {
        const int t0 = tile * 16;
        const int p0 = t0 & 8191;        // tile never crosses batch boundary

        int ic[2], i1[2], i2[2];
        const int pr = p0 + r;
        ic[0] = ids[t0 + r];
        i1[0] = (pr >= 1) ? ids[t0 + r - 1] : 500;
        i2[0] = (pr >= 2) ? ids[t0 + r - 2] : 500;
        ic[1] = ids[t0 + r + 8];
        i1[1] = ids[t0 + r + 7];
        i2[1] = ids[t0 + r + 6];

        float D1[32], D2[32], DK[64];
#pragma unroll
        for (int i = 0; i < 32; i++) { D1[i] = 0.f; D2[i] = 0.f; }
#pragma unroll
        for (int i = 0; i < 64; i++) DK[i] = 0.f;

        // -------- GEMM1: D1 = silu(T2 sums) @ W2_2 (k-permuted) --------
        for (int kt = 0; kt < 16; kt++) {
            uint32_t ah[4], al[4];
            const int cbs = kt * 16 + qq;
#pragma unroll
            for (int h = 0; h < 2; h++) {
                const float4 x = *(const float4*)(g_T2b + ic[h] * 256 + cbs);
                const float4 y = *(const float4*)(g_T2a + i1[h] * 256 + cbs);
                const float s0 = silu_f(x.x + y.x);
                const float s1 = silu_f(x.y + y.y);
                const float s2 = silu_f(x.z + y.z);
                const float s3 = silu_f(x.w + y.w);
                split2(s0, s1, ah[h],     al[h]);
                split2(s2, s3, ah[h + 2], al[h + 2]);
            }
#pragma unroll
            for (int nt = 0; nt < 8; nt++) {
                const uint4 q = Bs4[(kt * 8 + nt) * 32 + lane];
                mma16816(D1 + nt*4, ah, q.x, q.y);
                mma16816(D1 + nt*4, al, q.x, q.y);
                mma16816(D1 + nt*4, ah, q.z, q.w);
            }
        }

        // -------- GEMM2: D2 = silu(T3 sums) @ W2_3 (k-permuted) --------
        for (int kt = 0; kt < 16; kt++) {
            uint32_t ah[4], al[4];
            const int cbs = kt * 16 + qq;
#pragma unroll
            for (int h = 0; h < 2; h++) {
                const float4 x = *(const float4*)(g_T3c + ic[h] * 256 + cbs);
                const float4 y = *(const float4*)(g_T3b + i1[h] * 256 + cbs);
                const float4 z = *(const float4*)(g_T3a + i2[h] * 256 + cbs);
                const float s0 = silu_f(x.x + y.x + z.x);
                const float s1 = silu_f(x.y + y.y + z.y);
                const float s2 = silu_f(x.z + y.z + z.z);
                const float s3 = silu_f(x.w + y.w + z.w);
                split2(s0, s1, ah[h],     al[h]);
                split2(s2, s3, ah[h + 2], al[h + 2]);
            }
#pragma unroll
            for (int nt = 0; nt < 8; nt++) {
                const uint4 q = Bs4[4096 + (kt * 8 + nt) * 32 + lane];
                mma16816(D2 + nt*4, ah, q.x, q.y);
                mma16816(D2 + nt*4, al, q.x, q.y);
                mma16816(D2 + nt*4, ah, q.z, q.w);
            }
        }

        // ------- GEMM3: DK = emb @ [keyW|valW]; A = repacked D1/D2 -------
#pragma unroll
        for (int kt = 0; kt < 8; kt++) {
            const float* S = (kt < 4) ? D1 : D2;
            const int tb = (kt & 3) * 2;
            uint32_t ah[4], al[4];
            split2(S[tb*4+0], S[tb*4+1], ah[0], al[0]);
            split2(S[tb*4+2], S[tb*4+3], ah[1], al[1]);
            split2(S[tb*4+4], S[tb*4+5], ah[2], al[2]);
            split2(S[tb*4+6], S[tb*4+7], ah[3], al[3]);
#pragma unroll
            for (int nt = 0; nt < 16; nt++) {
                const uint4 q = Bs4[8192 + (kt * 16 + nt) * 32 + lane];
                mma16816(DK + nt*4, ah, q.x, q.y);
                mma16816(DK + nt*4, al, q.x, q.y);
                mma16816(DK + nt*4, ah, q.z, q.w);
            }
        }

        // ---------------- epilogue (per half-row) ----------------
#pragma unroll
        for (int h = 0; h < 2; h++) {
            const int t = t0 + r + 8 * h;
            float kd[16], s = 0.f, q = 0.f;
#pragma unroll
            for (int nt = 0; nt < 8; nt++) {
                const float2 kb = *(const float2*)(g_kvb + nt*8 + qc);
                const float u0 = DK[nt*4 + 2*h]     + kb.x;
                const float u1 = DK[nt*4 + 2*h + 1] + kb.y;
                kd[nt*2] = u0; kd[nt*2+1] = u1;
                s += u0 + u1;  q += u0*u0 + u1*u1;
            }
            s = qsum(s); q = qsum(q);
            const float mk = s * (1.f/64.f);
            const float ik = rsqrtf(q * (1.f/64.f) - mk*mk + 1e-5f);
            float hv[16], hs = 0.f, hq = 0.f;
#pragma unroll
            for (int nt = 0; nt < 8; nt++) {
                const float2 hh = *(const float2*)(hidden + (size_t)t*64 + nt*8 + qc);
                hv[nt*2] = hh.x; hv[nt*2+1] = hh.y;
                hs += hh.x + hh.y;  hq += hh.x*hh.x + hh.y*hh.y;
            }
            hs = qsum(hs); hq = qsum(hq);
            const float mh = hs * (1.f/64.f);
            const float ih = rsqrtf(hq * (1.f/64.f) - mh*mh + 1e-5f);
            float dp = 0.f;
#pragma unroll
            for (int nt = 0; nt < 8; nt++) {
                const int col = nt*8 + qc;
                const float2 ga = *(const float2*)(n1g + col);
                const float2 ba = *(const float2*)(n1b + col);
                const float2 gb = *(const float2*)(n2g + col);
                const float2 bbv = *(const float2*)(n2b + col);
                const float nk0 = (kd[nt*2]   - mk) * ik * ga.x + ba.x;
                const float nk1 = (kd[nt*2+1] - mk) * ik * ga.y + ba.y;
                const float nq0 = (hv[nt*2]   - mh) * ih * gb.x + bbv.x;
                const float nq1 = (hv[nt*2+1] - mh) * ih * gb.y + bbv.y;
                dp += nk0*nq0 + nk1*nq1;
            }
            dp = qsum(dp) * 0.125f;
            const float sq = sqrtf(fmaxf(fabsf(dp), 1e-6f));
            const float gs = (dp > 0.f) ? sq : ((dp < 0.f) ? -sq : 0.f);
            const float gate = __fdividef(1.f, 1.f + __expf(-gs));
            float gv[16], vs = 0.f, vq = 0.f;
#pragma unroll
            for (int nt = 8; nt < 16; nt++) {
                const float2 kb = *(const float2*)(g_kvb + nt*8 + qc);
                const float g0 = gate * (DK[nt*4 + 2*h]     + kb.x);
                const float g1 = gate * (DK[nt*4 + 2*h + 1] + kb.y);
                gv[(nt-8)*2] = g0; gv[(nt-8)*2+1] = g1;
                *(float2*)(g_Val + (size_t)t*64 + (nt-8)*8 + qc) = make_float2(g0, g1);
                vs += g0 + g1;  vq += g0*g0 + g1*g1;
            }
            vs = qsum(vs); vq = qsum(vq);
            const float mv = vs * (1.f/64.f);
            const float iv = rsqrtf(vq * (1.f/64.f) - mv*mv + 1e-5f);
#pragma unroll
            for (int nt = 0; nt < 8; nt++) {
                const int col = nt*8 + qc;
                const float2 gc = *(const float2*)(cg + col);
                const float2 bc = *(const float2*)(cb + col);
                const float v0 = (gv[nt*2]   - mv) * iv * gc.x + bc.x;
                const float v1 = (gv[nt*2+1] - mv) * iv * gc.y + bc.y;
                *(__half2*)(g_ValN + (size_t)t*64 + col) = __floats2half2_rn(v0, v1);
            }
        }
    }
}

// ---------------------------------------------------------------------------
// Kernel 4: streaming causal dilated depthwise conv (fp16 LN'd taps).
// Thread = (token, dim-quad): 4 dims per thread.
// ---------------------------------------------------------------------------
__global__ void conv_kernel(const float* __restrict__ cw,
                            float* __restrict__ out) {
    const int g     = blockIdx.x * blockDim.x + threadIdx.x;
    const int token = g >> 4;
    const int d0    = (g & 15) * 4;
    const int p     = token & 8191;

    float4 wd[4];
#pragma unroll
    for (int i = 0; i < 4; i++) wd[i] = *(const float4*)(cw + (d0 + i) * 4);

    float y0 = 0.f, y1 = 0.f, y2 = 0.f, y3 = 0.f;
    const __half* basen = g_ValN + (size_t)token * 64 + d0;
#pragma unroll
    for (int j = 0; j < 4; j++) {
        const int tp = p - 9 + 3 * j;
        if (tp >= 0) {
            const uint2 u = *(const uint2*)(basen + (long)(3 * j - 9) * 64);
            const float2 v01 = __half22float2(*(const __half2*)&u.x);
            const float2 v23 = __half22float2(*(const __half2*)&u.y);
            y0 += ((const float*)&wd[0])[j] * v01.x;
            y1 += ((const float*)&wd[1])[j] * v01.y;
            y2 += ((const float*)&wd[2])[j] * v23.x;
            y3 += ((const float*)&wd[3])[j] * v23.y;
        }
    }
    const float4 rr = __ldcs((const float4*)(g_Val + (size_t)token * 64 + d0));
    float4 o;
    o.x = rr.x + silu_f(y0);
    o.y = rr.y + silu_f(y1);
    o.z = rr.z + silu_f(y2);
    o.w = rr.w + silu_f(y3);
    __stcs((float4*)(out + (size_t)token * 64 + d0), o);
}

// ---------------------------------------------------------------------------
// Host launcher
// ---------------------------------------------------------------------------
extern "C" void kernel_launch(void* const* d_in, const int* in_sizes, int n_in,
                              void* d_out, int out_size) {
    const float* hidden = (const float*)d_in[0];
    const int*   ids    = (const int*)d_in[1];
    const float* emb    = (const float*)d_in[2];
    const float* W1_2   = (const float*)d_in[3];
    const float* b1_2   = (const float*)d_in[4];
    const float* W2_2   = (const float*)d_in[5];
    const float* b2_2   = (const float*)d_in[6];
    const float* W1_3   = (const float*)d_in[7];
    const float* b1_3   = (const float*)d_in[8];
    const float* W2_3   = (const float*)d_in[9];
    const float* b2_3   = (const float*)d_in[10];
    const float* keyW   = (const float*)d_in[11];
    const float* keyb   = (const float*)d_in[12];
    const float* valW   = (const float*)d_in[13];
    const float* valb   = (const float*)d_in[14];
    const float* n1g    = (const float*)d_in[15];
    const float* n1b    = (const float*)d_in[16];
    const float* n2g    = (const float*)d_in[17];
    const float* n2b    = (const float*)d_in[18];
    const float* cw     = (const float*)d_in[19];
    const float* cg     = (const float*)d_in[20];
    const float* cb     = (const float*)d_in[21];
    float* out = (float*)d_out;

    precompute_tables<<<501, 256>>>(emb, W1_2, b1_2, W1_3, b1_3);
    build_bimg<<<48, 256>>>(W2_2, W2_3, keyW, valW, b2_2, b2_3, keyb, valb);

    const size_t smem = 12288 * sizeof(uint4);  // 196608 B
    cudaFuncSetAttribute(main_kernel, cudaFuncAttributeMaxDynamicSharedMemorySize,
                         (int)smem);
    main_kernel<<<148, 512, smem>>>(ids, hidden, n1g, n1b, n2g, n2b, cg, cb);

    conv_kernel<<<NTOK * 16 / 256, 256>>>(cw, out);
}

// round 11
// speedup vs baseline: 3.3508x; 1.0409x over previous
#include <cuda_runtime.h>
#include <cuda_bf16.h>
#include <cuda_fp16.h>
#include <math.h>
#include <stdint.h>

#define BB    32
#define TT    8192
#define NTOK  (BB * TT)        // 262144
#define NTIL  (NTOK / 16)      // 16384 16-token tiles

// ---------------------------------------------------------------------------
// Device-global scratch
// ---------------------------------------------------------------------------
// Per-vocab tables, row 500 = zeros (causal pad). b1 folded into T2b/T3c.
__device__ float g_T2a[501 * 256];
__device__ float g_T2b[501 * 256];
__device__ float g_T3a[501 * 256];
__device__ float g_T3b[501 * 256];
__device__ float g_T3c[501 * 256];
__device__ float  g_Val [(size_t)NTOK * 64];
__device__ __half g_ValN[(size_t)NTOK * 64];
// Fused fragment images: per mma-tile, per lane, uint4 {hi0, hi1, lo0, lo1}.
// G1: tiles 0..127 @ 0; G2: @ 4096 uint4; G3: @ 8192 uint4.
// G1/G2 use the k-permuted layout (A loads its own float4); G3 is standard.
__device__ uint4 g_Bimg[12288];
// kv bias with emb-bias folded: kvb[n] = b2cat @ KVW[:,n] + (keyb|valb)[n]
__device__ float g_kvb[128];

__device__ __forceinline__ float silu_f(float x) {
    return __fdividef(x, 1.0f + __expf(-x));
}
__device__ __forceinline__ float qsum(float v) {   // sum over quad (4 lanes)
    v += __shfl_xor_sync(0xffffffffu, v, 1);
    v += __shfl_xor_sync(0xffffffffu, v, 2);
    return v;
}
// hi/lo bf16 split of a float pair -> packed bf16x2 regs
__device__ __forceinline__ void split2(float a, float b, uint32_t& hi, uint32_t& lo) {
    __nv_bfloat162 h = __floats2bfloat162_rn(a, b);
    __nv_bfloat162 l = __floats2bfloat162_rn(a - __low2float(h), b - __high2float(h));
    hi = *(uint32_t*)&h;
    lo = *(uint32_t*)&l;
}
__device__ __forceinline__ void mma16816(float* d, const uint32_t* a,
                                         uint32_t b0, uint32_t b1) {
    asm volatile(
        "mma.sync.aligned.m16n8k16.row.col.f32.bf16.bf16.f32 "
        "{%0,%1,%2,%3}, {%4,%5,%6,%7}, {%8,%9}, {%0,%1,%2,%3};"
        : "+f"(d[0]), "+f"(d[1]), "+f"(d[2]), "+f"(d[3])
        : "r"(a[0]), "r"(a[1]), "r"(a[2]), "r"(a[3]), "r"(b0), "r"(b1));
}

// ---------------------------------------------------------------------------
// Kernel 1 (merged prep): blocks 0..500 build per-vocab tables (row 500 = 0);
// blocks 501..548 build fused-fragment B images; block 501 also folds kv bias.
// ---------------------------------------------------------------------------
__global__ void prep_kernel(const float* __restrict__ emb,
                            const float* __restrict__ W1_2,
                            const float* __restrict__ b1_2,
                            const float* __restrict__ W1_3,
                            const float* __restrict__ b1_3,
                            const float* __restrict__ W2_2,
                            const float* __restrict__ W2_3,
                            const float* __restrict__ keyW,
                            const float* __restrict__ valW,
                            const float* __restrict__ b2_2,
                            const float* __restrict__ b2_3,
                            const float* __restrict__ keyb,
                            const float* __restrict__ valb) {
    if (blockIdx.x <= 500) {
        __shared__ float e[64];
        const int id = blockIdx.x, o = threadIdx.x;
        if (id == 500) {
            g_T2a[id*256+o] = 0.f; g_T2b[id*256+o] = 0.f;
            g_T3a[id*256+o] = 0.f; g_T3b[id*256+o] = 0.f; g_T3c[id*256+o] = 0.f;
            return;
        }
        if (o < 64) e[o] = emb[id * 64 + o];
        __syncthreads();
        float a2=0.f, b2=0.f, a3=0.f, b3=0.f, c3=0.f;
#pragma unroll 8
        for (int d = 0; d < 64; d++) {
            const float ev = e[d];
            a2 += ev * W1_2[d*256 + o];
            b2 += ev * W1_2[(64+d)*256 + o];
            a3 += ev * W1_3[d*256 + o];
            b3 += ev * W1_3[(64+d)*256 + o];
            c3 += ev * W1_3[(128+d)*256 + o];
        }
        g_T2a[id*256+o] = a2;  g_T2b[id*256+o] = b2 + b1_2[o];
        g_T3a[id*256+o] = a3;  g_T3b[id*256+o] = b3;
        g_T3c[id*256+o] = c3 + b1_3[o];
        return;
    }

    // ---- B-image builder (48 blocks x 256 = 12288 entries) ----
    const int idx = (blockIdx.x - 501) * blockDim.x + threadIdx.x;
    if (idx < 12288) {
        const int g    = idx >> 12;
        const int tile = (idx >> 5) & 127;
        const int lane = idx & 31;
        const int NT = (g == 2) ? 16 : 8;
        const int kt = tile / NT, nt = tile % NT;
        const int n  = nt*8 + (lane >> 2);
        int ka, kb, kc, kd;
        if (g < 2) {   // k-permuted: contiguous quad feeds A-fragment float4
            const int k0 = kt*16 + (lane & 3)*4;
            ka = k0; kb = k0+1; kc = k0+2; kd = k0+3;
        } else {       // standard mma B layout
            const int k0 = kt*16 + (lane & 3)*2;
            ka = k0; kb = k0+1; kc = k0+8; kd = k0+9;
        }
        float w00, w01, w10, w11;
        if (g == 0) {
            w00 = W2_2[ka*64+n]; w01 = W2_2[kb*64+n];
            w10 = W2_2[kc*64+n]; w11 = W2_2[kd*64+n];
        } else if (g == 1) {
            w00 = W2_3[ka*64+n]; w01 = W2_3[kb*64+n];
            w10 = W2_3[kc*64+n]; w11 = W2_3[kd*64+n];
        } else if (n < 64) {
            w00 = keyW[ka*64+n]; w01 = keyW[kb*64+n];
            w10 = keyW[kc*64+n]; w11 = keyW[kd*64+n];
        } else {
            w00 = valW[ka*64+n-64]; w01 = valW[kb*64+n-64];
            w10 = valW[kc*64+n-64]; w11 = valW[kd*64+n-64];
        }
        uint4 q;
        split2(w00, w01, q.x, q.z);
        split2(w10, w11, q.y, q.w);
        g_Bimg[idx] = q;
    }
    if (blockIdx.x == 501 && threadIdx.x < 128) {
        const int nn = threadIdx.x;
        float s = (nn < 64) ? keyb[nn] : valb[nn - 64];
        for (int jj = 0; jj < 128; jj++) {
            const float bj = (jj < 64) ? b2_2[jj] : b2_3[jj - 64];
            const float w  = (nn < 64) ? keyW[jj*64 + nn] : valW[jj*64 + nn - 64];
            s += bj * w;
        }
        g_kvb[nn] = s;
    }
}

// ---------------------------------------------------------------------------
// Kernel 2: main fused kernel. 148 CTAs x 512 thr (16 warps); warp = 16 tokens.
// Phase order minimizes live registers: GEMM1 -> GEMM3a(D1) -> GEMM2 -> GEMM3b(D2).
// ---------------------------------------------------------------------------
__global__ void __launch_bounds__(512, 1)
main_kernel(const int*   __restrict__ ids,
            const float* __restrict__ hidden,
            const float* __restrict__ n1g, const float* __restrict__ n1b,
            const float* __restrict__ n2g, const float* __restrict__ n2b,
            const float* __restrict__ cg,  const float* __restrict__ cb) {
    extern __shared__ uint4 Bs4[];   // 12288 uint4 = 192 KB
    for (int i = threadIdx.x; i < 12288; i += 512) Bs4[i] = g_Bimg[i];
    __syncthreads();

    const int wid  = threadIdx.x >> 5;
    const int lane = threadIdx.x & 31;
    const int r    = lane >> 2;          // fragment row (0..7)
    const int qc   = (lane & 3) * 2;     // fragment col base (0,2,4,6)
    const int qq   = (lane & 3) * 4;     // permuted-gather col base (0,4,8,12)
    const int gw   = blockIdx.x * 16 + wid;

    for (int tile = gw; tile < NTIL; tile += 148 * 16) {
        const int t0 = tile * 16;
        const int p0 = t0 & 8191;        // tile never crosses batch boundary

        int ic[2], i1[2], i2[2];
        const int pr = p0 + r;
        ic[0] = ids[t0 + r];
        i1[0] = (pr >= 1) ? ids[t0 + r - 1] : 500;
        i2[0] = (pr >= 2) ? ids[t0 + r - 2] : 500;
        ic[1] = ids[t0 + r + 8];
        i1[1] = ids[t0 + r + 7];
        i2[1] = ids[t0 + r + 6];

        float DK[64];
#pragma unroll
        for (int i = 0; i < 64; i++) DK[i] = 0.f;

        // ================= phase A: D1 = silu(T2 sums) @ W2_2 =================
        {
            float D1[32];
#pragma unroll
            for (int i = 0; i < 32; i++) D1[i] = 0.f;
            for (int kt = 0; kt < 16; kt++) {
                uint32_t ah[4], al[4];
                const int cbs = kt * 16 + qq;
#pragma unroll
                for (int h = 0; h < 2; h++) {
                    const float4 x = *(const float4*)(g_T2b + ic[h] * 256 + cbs);
                    const float4 y = *(const float4*)(g_T2a + i1[h] * 256 + cbs);
                    split2(silu_f(x.x + y.x), silu_f(x.y + y.y), ah[h],     al[h]);
                    split2(silu_f(x.z + y.z), silu_f(x.w + y.w), ah[h + 2], al[h + 2]);
                }
#pragma unroll
                for (int nt = 0; nt < 8; nt++) {
                    const uint4 q = Bs4[(kt * 8 + nt) * 32 + lane];
                    mma16816(D1 + nt*4, ah, q.x, q.y);
                    mma16816(D1 + nt*4, al, q.x, q.y);
                    mma16816(D1 + nt*4, ah, q.z, q.w);
                }
            }
            // ---- phase A2: GEMM3a consumes D1 (k-tiles 0..3) ----
#pragma unroll
            for (int kt = 0; kt < 4; kt++) {
                const int tb = kt * 2;
                uint32_t ah[4], al[4];
                split2(D1[tb*4+0], D1[tb*4+1], ah[0], al[0]);
                split2(D1[tb*4+2], D1[tb*4+3], ah[1], al[1]);
                split2(D1[tb*4+4], D1[tb*4+5], ah[2], al[2]);
                split2(D1[tb*4+6], D1[tb*4+7], ah[3], al[3]);
#pragma unroll
                for (int nt = 0; nt < 16; nt++) {
                    const uint4 q = Bs4[8192 + (kt * 16 + nt) * 32 + lane];
                    mma16816(DK + nt*4, ah, q.x, q.y);
                    mma16816(DK + nt*4, al, q.x, q.y);
                    mma16816(DK + nt*4, ah, q.z, q.w);
                }
            }
        }

        // ================= phase B: D2 = silu(T3 sums) @ W2_3 =================
        {
            float D2[32];
#pragma unroll
            for (int i = 0; i < 32; i++) D2[i] = 0.f;
            for (int kt = 0; kt < 16; kt++) {
                uint32_t ah[4], al[4];
                const int cbs = kt * 16 + qq;
#pragma unroll
                for (int h = 0; h < 2; h++) {
                    const float4 x = *(const float4*)(g_T3c + ic[h] * 256 + cbs);
                    const float4 y = *(const float4*)(g_T3b + i1[h] * 256 + cbs);
                    const float4 z = *(const float4*)(g_T3a + i2[h] * 256 + cbs);
                    split2(silu_f(x.x + y.x + z.x), silu_f(x.y + y.y + z.y),
                           ah[h],     al[h]);
                    split2(silu_f(x.z + y.z + z.z), silu_f(x.w + y.w + z.w),
                           ah[h + 2], al[h + 2]);
                }
#pragma unroll
                for (int nt = 0; nt < 8; nt++) {
                    const uint4 q = Bs4[4096 + (kt * 8 + nt) * 32 + lane];
                    mma16816(D2 + nt*4, ah, q.x, q.y);
                    mma16816(D2 + nt*4, al, q.x, q.y);
                    mma16816(D2 + nt*4, ah, q.z, q.w);
                }
            }
            // ---- phase B2: GEMM3b consumes D2 (k-tiles 4..7) ----
#pragma unroll
            for (int kt = 4; kt < 8; kt++) {
                const int tb = (kt & 3) * 2;
                uint32_t ah[4], al[4];
                split2(D2[tb*4+0], D2[tb*4+1], ah[0], al[0]);
                split2(D2[tb*4+2], D2[tb*4+3], ah[1], al[1]);
                split2(D2[tb*4+4], D2[tb*4+5], ah[2], al[2]);
                split2(D2[tb*4+6], D2[tb*4+7], ah[3], al[3]);
#pragma unroll
                for (int nt = 0; nt < 16; nt++) {
                    const uint4 q = Bs4[8192 + (kt * 16 + nt) * 32 + lane];
                    mma16816(DK + nt*4, ah, q.x, q.y);
                    mma16816(DK + nt*4, al, q.x, q.y);
                    mma16816(DK + nt*4, ah, q.z, q.w);
                }
            }
        }

        // ---------------- epilogue (per half-row) ----------------
#pragma unroll
        for (int h = 0; h < 2; h++) {
            const int t = t0 + r + 8 * h;
            float kd[16], s = 0.f, q = 0.f;
#pragma unroll
            for (int nt = 0; nt < 8; nt++) {
                const float2 kb = *(const float2*)(g_kvb + nt*8 + qc);
                const float u0 = DK[nt*4 + 2*h]     + kb.x;
                const float u1 = DK[nt*4 + 2*h + 1] + kb.y;
                kd[nt*2] = u0; kd[nt*2+1] = u1;
                s += u0 + u1;  q += u0*u0 + u1*u1;
            }
            s = qsum(s); q = qsum(q);
            const float mk = s * (1.f/64.f);
            const float ik = rsqrtf(q * (1.f/64.f) - mk*mk + 1e-5f);
            float hv[16], hs = 0.f, hq = 0.f;
#pragma unroll
            for (int nt = 0; nt < 8; nt++) {
                const float2 hh = *(const float2*)(hidden + (size_t)t*64 + nt*8 + qc);
                hv[nt*2] = hh.x; hv[nt*2+1] = hh.y;
                hs += hh.x + hh.y;  hq += hh.x*hh.x + hh.y*hh.y;
            }
            hs = qsum(hs); hq = qsum(hq);
            const float mh = hs * (1.f/64.f);
            const float ih = rsqrtf(hq * (1.f/64.f) - mh*mh + 1e-5f);
            float dp = 0.f;
#pragma unroll
            for (int nt = 0; nt < 8; nt++) {
                const int col = nt*8 + qc;
                const float2 ga = *(const float2*)(n1g + col);
                const float2 ba = *(const float2*)(n1b + col);
                const float2 gb = *(const float2*)(n2g + col);
                const float2 bbv = *(const float2*)(n2b + col);
                const float nk0 = (kd[nt*2]   - mk) * ik * ga.x + ba.x;
                const float nk1 = (kd[nt*2+1] - mk) * ik * ga.y + ba.y;
                const float nq0 = (hv[nt*2]   - mh) * ih * gb.x + bbv.x;
                const float nq1 = (hv[nt*2+1] - mh) * ih * gb.y + bbv.y;
                dp += nk0*nq0 + nk1*nq1;
            }
            dp = qsum(dp) * 0.125f;
            const float sq = sqrtf(fmaxf(fabsf(dp), 1e-6f));
            const float gs = (dp > 0.f) ? sq : ((dp < 0.f) ? -sq : 0.f);
            const float gate = __fdividef(1.f, 1.f + __expf(-gs));
            float gv[16], vs = 0.f, vq = 0.f;
#pragma unroll
            for (int nt = 8; nt < 16; nt++) {
                const float2 kb = *(const float2*)(g_kvb + nt*8 + qc);
                const float g0 = gate * (DK[nt*4 + 2*h]     + kb.x);
                const float g1 = gate * (DK[nt*4 + 2*h + 1] + kb.y);
                gv[(nt-8)*2] = g0; gv[(nt-8)*2+1] = g1;
                *(float2*)(g_Val + (size_t)t*64 + (nt-8)*8 + qc) = make_float2(g0, g1);
                vs += g0 + g1;  vq += g0*g0 + g1*g1;
            }
            vs = qsum(vs); vq = qsum(vq);
            const float mv = vs * (1.f/64.f);
            const float iv = rsqrtf(vq * (1.f/64.f) - mv*mv + 1e-5f);
#pragma unroll
            for (int nt = 0; nt < 8; nt++) {
                const int col = nt*8 + qc;
                const float2 gc = *(const float2*)(cg + col);
                const float2 bc = *(const float2*)(cb + col);
                const float v0 = (gv[nt*2]   - mv) * iv * gc.x + bc.x;
                const float v1 = (gv[nt*2+1] - mv) * iv * gc.y + bc.y;
                *(__half2*)(g_ValN + (size_t)t*64 + col) = __floats2half2_rn(v0, v1);
            }
        }
    }
}

// ---------------------------------------------------------------------------
// Kernel 3: streaming causal dilated depthwise conv (fp16 LN'd taps).
// Warp per token, 2 dims per thread (R9 shape — fastest measured).
// ---------------------------------------------------------------------------
__global__ void conv_kernel(const float* __restrict__ cw,
                            float* __restrict__ out) {
    const int g     = blockIdx.x * blockDim.x + threadIdx.x;
    const int token = g >> 5;
    const int d0    = (g & 31) * 2;
    const int p     = token & 8191;

    const float4 w0 = *(const float4*)(cw + d0 * 4);
    const float4 w1 = *(const float4*)(cw + d0 * 4 + 4);

    float y0 = 0.f, y1 = 0.f;
    const __half* basen = g_ValN + (size_t)token * 64 + d0;
#pragma unroll
    for (int j = 0; j < 4; j++) {
        const int tp = p - 9 + 3 * j;
        if (tp >= 0) {
            const __half2 vh = *(const __half2*)(basen + (long)(3 * j - 9) * 64);
            const float2 v = __half22float2(vh);
            y0 += ((const float*)&w0)[j] * v.x;
            y1 += ((const float*)&w1)[j] * v.y;
        }
    }
    const float2 rr = __ldcs((const float2*)(g_Val + (size_t)token * 64 + d0));
    __stcs((float2*)(out + (size_t)token * 64 + d0),
           make_float2(rr.x + silu_f(y0), rr.y + silu_f(y1)));
}

// ---------------------------------------------------------------------------
// Host launcher
// ---------------------------------------------------------------------------
extern "C" void kernel_launch(void* const* d_in, const int* in_sizes, int n_in,
                              void* d_out, int out_size) {
    const float* hidden = (const float*)d_in[0];
    const int*   ids    = (const int*)d_in[1];
    const float* emb    = (const float*)d_in[2];
    const float* W1_2   = (const float*)d_in[3];
    const float* b1_2   = (const float*)d_in[4];
    const float* W2_2   = (const float*)d_in[5];
    const float* b2_2   = (const float*)d_in[6];
    const float* W1_3   = (const float*)d_in[7];
    const float* b1_3   = (const float*)d_in[8];
    const float* W2_3   = (const float*)d_in[9];
    const float* b2_3   = (const float*)d_in[10];
    const float* keyW   = (const float*)d_in[11];
    const float* keyb   = (const float*)d_in[12];
    const float* valW   = (const float*)d_in[13];
    const float* valb   = (const float*)d_in[14];
    const float* n1g    = (const float*)d_in[15];
    const float* n1b    = (const float*)d_in[16];
    const float* n2g    = (const float*)d_in[17];
    const float* n2b    = (const float*)d_in[18];
    const float* cw     = (const float*)d_in[19];
    const float* cg     = (const float*)d_in[20];
    const float* cb     = (const float*)d_in[21];
    float* out = (float*)d_out;

    prep_kernel<<<549, 256>>>(emb, W1_2, b1_2, W1_3, b1_3,
                              W2_2, W2_3, keyW, valW,
                              b2_2, b2_3, keyb, valb);

    const size_t smem = 12288 * sizeof(uint4);  // 196608 B
    cudaFuncSetAttribute(main_kernel, cudaFuncAttributeMaxDynamicSharedMemorySize,
                         (int)smem);
    main_kernel<<<148, 512, smem>>>(ids, hidden, n1g, n1b, n2g, n2b, cg, cb);

    conv_kernel<<<NTOK * 32 / 256, 256>>>(cw, out);
}